// round 6
// baseline (speedup 1.0000x reference)
#include <cuda_runtime.h>
#include <cstdint>

// Problem constants
#define S_LEN  2048
#define DIMV   1024
#define NHEAD  16
#define HD     64
#define BATCH  2
#define M_ROWS (BATCH * S_LEN)     // 4096
#define KDIM   1024
#define NDIM   1024
#define BHEADS (BATCH * NHEAD)     // 32
#define CHUNK  128
#define NCHUNK (S_LEN / CHUNK)     // 16
#define WSZ    (NDIM * KDIM)       // one weight matrix

// ---------------------------------------------------------------------------
// Scratch (static device globals: allocation-free per harness rules)
// ---------------------------------------------------------------------------
__device__ float g_q[M_ROWS * DIMV];
__device__ float g_k[M_ROWS * DIMV];
__device__ float g_v[M_ROWS * DIMV];
__device__ float g_att[M_ROWS * DIMV];
__device__ float g_ah[M_ROWS * KDIM];   // activation hi split (x, then att)
__device__ float g_al[M_ROWS * KDIM];   // activation lo split
__device__ float g_wh[4 * WSZ];         // weight hi splits: Wq,Wk,Wv,Wo
__device__ float g_wl[4 * WSZ];         // weight lo splits
__device__ float g_ckv[BHEADS * NCHUNK * HD * HD];
__device__ float g_ck1[BHEADS * NCHUNK * HD];
__device__ float g_pkv[BHEADS * NCHUNK * HD * HD];
__device__ float g_pk1[BHEADS * NCHUNK * HD];

#define SMS 132  // padded shared stride for the fp32 attention kernels

// ===========================================================================
// Helpers
// ===========================================================================
__device__ __forceinline__ uint32_t smem_u32(const void* p) {
    uint32_t a;
    asm("{ .reg .u64 t; cvta.to.shared.u64 t, %1; cvt.u32.u64 %0, t; }"
        : "=r"(a) : "l"(p));
    return a;
}

__device__ __forceinline__ float tf32f(float f) {
    uint32_t r;
    asm("cvt.rna.tf32.f32 %0, %1;" : "=r"(r) : "f"(f));
    return __uint_as_float(r);
}

__device__ __forceinline__ void cp16(uint32_t saddr, const void* g) {
    asm volatile("cp.async.cg.shared.global [%0], [%1], 16;"
                 :: "r"(saddr), "l"(g));
}
#define CP_COMMIT() asm volatile("cp.async.commit_group;" ::: "memory")
#define CP_WAIT1()  asm volatile("cp.async.wait_group 1;" ::: "memory")

__device__ __forceinline__ void mma_tf32(float* d, const uint32_t* a,
                                         uint32_t b0, uint32_t b1) {
    asm volatile(
        "mma.sync.aligned.m16n8k8.row.col.f32.tf32.tf32.f32 "
        "{%0,%1,%2,%3}, {%4,%5,%6,%7}, {%8,%9}, {%0,%1,%2,%3};"
        : "+f"(d[0]), "+f"(d[1]), "+f"(d[2]), "+f"(d[3])
        : "r"(a[0]), "r"(a[1]), "r"(a[2]), "r"(a[3]), "r"(b0), "r"(b1));
}

// ---------------------------------------------------------------------------
// Split prep: hi = rna_tf32(v), lo = rna_tf32(v - hi)
// Specialized entry points so kernel_launch needs no symbol-address queries.
// ---------------------------------------------------------------------------
__device__ __forceinline__ void split_body(
    const float* __restrict__ src, float* __restrict__ hi,
    float* __restrict__ lo, int n4)
{
    int i = blockIdx.x * blockDim.x + threadIdx.x;
    const int stride = gridDim.x * blockDim.x;
    const float4* s4 = (const float4*)src;
    float4* h4 = (float4*)hi;
    float4* l4 = (float4*)lo;
    for (; i < n4; i += stride) {
        float4 v = s4[i];
        float4 h, l;
        h.x = tf32f(v.x); l.x = tf32f(v.x - h.x);
        h.y = tf32f(v.y); l.y = tf32f(v.y - h.y);
        h.z = tf32f(v.z); l.z = tf32f(v.z - h.z);
        h.w = tf32f(v.w); l.w = tf32f(v.w - h.w);
        h4[i] = h; l4[i] = l;
    }
}

__global__ void __launch_bounds__(256) split_act_kernel(const float* __restrict__ src)
{
    split_body(src, g_ah, g_al, M_ROWS * KDIM / 4);
}

__global__ void __launch_bounds__(256) split_att_kernel()
{
    split_body(g_att, g_ah, g_al, M_ROWS * KDIM / 4);
}

__global__ void __launch_bounds__(256) split_w_kernel(const float* __restrict__ src, int slot)
{
    split_body(src, g_wh + (size_t)slot * WSZ, g_wl + (size_t)slot * WSZ, WSZ / 4);
}

// ===========================================================================
// 3xTF32 GEMM on pre-split operands, cp.async 3-stage pipeline.
// C[m,n] = sum_k A[m,k]*W[n,k] + bias[n], optional exp epilogue.
// CTA 128x128, 256 threads, 8 warps (2x4 grid, 64x32 warp tiles), BK=16.
// ===========================================================================
#define BK    16
#define NKST  (KDIM / BK)     // 64
#define RST   20              // padded row stride (words)
#define MATW  (128 * RST)     // 2560 words per matrix per stage
#define STGW  (4 * MATW)      // Ah, Al, Bh, Bl
#define NST   3
#define GEMM_SMEM (NST * STGW * 4)   // 122880 bytes

__device__ __forceinline__ void gemm_split(
    const float* __restrict__ Ah, const float* __restrict__ Al,
    const float* __restrict__ Bh, const float* __restrict__ Bl,
    const float* __restrict__ bias, float* __restrict__ out, int doExp,
    int m0, int n0)
{
    extern __shared__ float sh[];
    const uint32_t shb = smem_u32(sh);

    const int tid = threadIdx.x;
    const int lane = tid & 31, wid = tid >> 5;
    const int wm = wid >> 2, wn = wid & 3;       // 2 x 4 warp grid
    const int grp = lane >> 2, tig = lane & 3;
    const int r = tid >> 1, half = tid & 1;      // load coords

    const float* pAh = Ah + (size_t)(m0 + r) * KDIM + half * 8;
    const float* pAl = Al + (size_t)(m0 + r) * KDIM + half * 8;
    const float* pBh = Bh + (size_t)(n0 + r) * KDIM + half * 8;
    const float* pBl = Bl + (size_t)(n0 + r) * KDIM + half * 8;
    const uint32_t sa0 = shb + 4u * (uint32_t)(r * RST + half * 8);

    float acc[4][4][4];
#pragma unroll
    for (int mt = 0; mt < 4; mt++)
#pragma unroll
        for (int nt = 0; nt < 4; nt++)
#pragma unroll
            for (int e = 0; e < 4; e++) acc[mt][nt][e] = 0.f;

#define ISSUE(s_) do {                                                     \
    const int s__ = (s_);                                                  \
    const int k0__ = s__ * BK;                                             \
    const uint32_t sb__ = sa0 + (uint32_t)((s__ % NST) * STGW) * 4u;       \
    cp16(sb__,                 pAh + k0__);                                \
    cp16(sb__ + 16,            pAh + k0__ + 4);                            \
    cp16(sb__ + 4u*MATW,       pAl + k0__);                                \
    cp16(sb__ + 4u*MATW + 16,  pAl + k0__ + 4);                            \
    cp16(sb__ + 8u*MATW,       pBh + k0__);                                \
    cp16(sb__ + 8u*MATW + 16,  pBh + k0__ + 4);                            \
    cp16(sb__ + 12u*MATW,      pBl + k0__);                                \
    cp16(sb__ + 12u*MATW + 16, pBl + k0__ + 4);                            \
    CP_COMMIT();                                                           \
} while (0)

    ISSUE(0);
    ISSUE(1);

    for (int s = 0; s < NKST; s++) {
        CP_WAIT1();
        __syncthreads();
        if (s + 2 < NKST) ISSUE(s + 2);

        const uint32_t* bu = (const uint32_t*)(sh + (s % NST) * STGW);
#pragma unroll
        for (int kk = 0; kk < BK; kk += 8) {
            const int c = kk + tig;
            uint32_t ah[4][4], al[4][4];
#pragma unroll
            for (int mt = 0; mt < 4; mt++) {
                const int ro = (wm * 64 + mt * 16 + grp) * RST;
                ah[mt][0] = bu[ro + c];
                ah[mt][1] = bu[ro + 8 * RST + c];
                ah[mt][2] = bu[ro + c + 4];
                ah[mt][3] = bu[ro + 8 * RST + c + 4];
                al[mt][0] = bu[MATW + ro + c];
                al[mt][1] = bu[MATW + ro + 8 * RST + c];
                al[mt][2] = bu[MATW + ro + c + 4];
                al[mt][3] = bu[MATW + ro + 8 * RST + c + 4];
            }
#pragma unroll
            for (int nt = 0; nt < 4; nt++) {
                const int ro = (wn * 32 + nt * 8 + grp) * RST;
                const uint32_t bh0 = bu[2 * MATW + ro + c];
                const uint32_t bh1 = bu[2 * MATW + ro + c + 4];
                const uint32_t bl0 = bu[3 * MATW + ro + c];
                const uint32_t bl1 = bu[3 * MATW + ro + c + 4];
#pragma unroll
                for (int mt = 0; mt < 4; mt++) {
                    mma_tf32(acc[mt][nt], ah[mt], bh0, bh1);
                    mma_tf32(acc[mt][nt], ah[mt], bl0, bl1);
                    mma_tf32(acc[mt][nt], al[mt], bh0, bh1);
                }
            }
        }
    }
#undef ISSUE

    // epilogue
#pragma unroll
    for (int mt = 0; mt < 4; mt++) {
        const int rr = m0 + wm * 64 + mt * 16 + grp;
#pragma unroll
        for (int nt = 0; nt < 4; nt++) {
            const int cc = n0 + wn * 32 + nt * 8 + 2 * tig;
            const float bb0 = bias[cc], bb1 = bias[cc + 1];
            float v0 = acc[mt][nt][0] + bb0;
            float v1 = acc[mt][nt][1] + bb1;
            float v2 = acc[mt][nt][2] + bb0;
            float v3 = acc[mt][nt][3] + bb1;
            if (doExp) {
                v0 = expf(v0); v1 = expf(v1); v2 = expf(v2); v3 = expf(v3);
            }
            float2 p0; p0.x = v0; p0.y = v1;
            float2 p1; p1.x = v2; p1.y = v3;
            *(float2*)&out[(size_t)rr * NDIM + cc]       = p0;
            *(float2*)&out[(size_t)(rr + 8) * NDIM + cc] = p1;
        }
    }
}

__global__ void __launch_bounds__(256) qkv_mma_kernel(
    const float* __restrict__ bq, const float* __restrict__ bk,
    const float* __restrict__ bv)
{
    const int z = blockIdx.z;
    const float* bias = (z == 0) ? bq : ((z == 1) ? bk : bv);
    float* out        = (z == 0) ? g_q : ((z == 1) ? g_k : g_v);
    gemm_split(g_ah, g_al, g_wh + (size_t)z * WSZ, g_wl + (size_t)z * WSZ,
               bias, out, z < 2, blockIdx.y * 128, blockIdx.x * 128);
}

__global__ void __launch_bounds__(256) out_mma_kernel(
    const float* __restrict__ bo, float* __restrict__ out)
{
    gemm_split(g_ah, g_al, g_wh + (size_t)3 * WSZ, g_wl + (size_t)3 * WSZ,
               bo, out, 0, blockIdx.y * 128, blockIdx.x * 128);
}

// ---------------------------------------------------------------------------
// Chunk stats: per (head, chunk) compute sum_t k_t v_t^T (64x64) and sum_t k_t
// ---------------------------------------------------------------------------
__global__ void __launch_bounds__(256) chunk_stats_kernel()
{
    extern __shared__ __align__(16) float sm[];
    float* Ks = sm;
    float* Vs = sm + CHUNK * HD;
    const int bh = blockIdx.y, c = blockIdx.x;
    const int b = bh >> 4, h = bh & 15;
    const int tid = threadIdx.x;
    const size_t base = ((size_t)(b * S_LEN + c * CHUNK)) * DIMV + h * HD;

#pragma unroll
    for (int it = 0; it < 8; it++) {
        const int idx = tid + it * 256;
        const int t = idx >> 4, dv = idx & 15;
        *(float4*)&Ks[t * HD + dv * 4] =
            *(const float4*)(g_k + base + (size_t)t * DIMV + dv * 4);
        *(float4*)&Vs[t * HD + dv * 4] =
            *(const float4*)(g_v + base + (size_t)t * DIMV + dv * 4);
    }
    __syncthreads();

    const int tx = tid & 15, ty = tid >> 4;
    float acc[4][4];
#pragma unroll
    for (int i = 0; i < 4; i++)
#pragma unroll
        for (int j = 0; j < 4; j++) acc[i][j] = 0.f;

#pragma unroll 4
    for (int t = 0; t < CHUNK; t++) {
        float kf[4], vf[4];
        *(float4*)kf = *(const float4*)&Ks[t * HD + ty * 4];
        *(float4*)vf = *(const float4*)&Vs[t * HD + tx * 4];
#pragma unroll
        for (int i = 0; i < 4; i++)
#pragma unroll
            for (int j = 0; j < 4; j++)
                acc[i][j] = fmaf(kf[i], vf[j], acc[i][j]);
    }

    float* okv = g_ckv + ((size_t)bh * NCHUNK + c) * HD * HD;
#pragma unroll
    for (int i = 0; i < 4; i++)
        *(float4*)&okv[(ty * 4 + i) * HD + tx * 4] = *(float4*)acc[i];

    if (tid < HD) {
        float s = 0.f;
#pragma unroll 8
        for (int t = 0; t < CHUNK; t++) s += Ks[t * HD + tid];
        g_ck1[((size_t)bh * NCHUNK + c) * HD + tid] = s;
    }
}

// ---------------------------------------------------------------------------
// Exclusive prefix over the 16 chunk states per head
// ---------------------------------------------------------------------------
__global__ void __launch_bounds__(256) prefix_kernel()
{
    const int bh = blockIdx.x, tid = threadIdx.x;
    for (int e = tid; e < HD * HD; e += 256) {
        float run = 0.f;
#pragma unroll
        for (int c = 0; c < NCHUNK; c++) {
            const size_t off = ((size_t)bh * NCHUNK + c) * HD * HD + e;
            g_pkv[off] = run;
            run += g_ckv[off];
        }
    }
    if (tid < HD) {
        float run = 0.f;
#pragma unroll
        for (int c = 0; c < NCHUNK; c++) {
            const size_t off = ((size_t)bh * NCHUNK + c) * HD + tid;
            g_pk1[off] = run;
            run += g_ck1[off];
        }
    }
}

// ---------------------------------------------------------------------------
// Chunk output: out_t = (q_t @ KVprev + sum_{t'<=t} (q_t.k_t') v_t') / den_t
// ---------------------------------------------------------------------------
__global__ void __launch_bounds__(256) chunk_out_kernel()
{
    extern __shared__ __align__(16) float sm[];
    float* QsT  = sm;
    float* KsT  = QsT + HD * SMS;
    float* Vs   = KsT + HD * SMS;
    float* Sp   = Vs + CHUNK * HD;
    float* Am   = Sp + HD * HD;
    float* k1p  = Am + CHUNK * SMS;
    float* dens = k1p + HD;

    const int bh = blockIdx.y, c = blockIdx.x;
    const int b = bh >> 4, h = bh & 15;
    const int tid = threadIdx.x;
    const size_t base = ((size_t)(b * S_LEN + c * CHUNK)) * DIMV + h * HD;

#pragma unroll
    for (int it = 0; it < 8; it++) {
        const int idx = tid + it * 256;
        const int t = idx >> 4, dv = idx & 15;
        float4 q4 = *(const float4*)(g_q + base + (size_t)t * DIMV + dv * 4);
        float4 k4 = *(const float4*)(g_k + base + (size_t)t * DIMV + dv * 4);
        float4 v4 = *(const float4*)(g_v + base + (size_t)t * DIMV + dv * 4);
        QsT[(dv * 4 + 0) * SMS + t] = q4.x;
        QsT[(dv * 4 + 1) * SMS + t] = q4.y;
        QsT[(dv * 4 + 2) * SMS + t] = q4.z;
        QsT[(dv * 4 + 3) * SMS + t] = q4.w;
        KsT[(dv * 4 + 0) * SMS + t] = k4.x;
        KsT[(dv * 4 + 1) * SMS + t] = k4.y;
        KsT[(dv * 4 + 2) * SMS + t] = k4.z;
        KsT[(dv * 4 + 3) * SMS + t] = k4.w;
        *(float4*)&Vs[t * HD + dv * 4] = v4;
    }
    {
        const float* spg = g_pkv + ((size_t)bh * NCHUNK + c) * HD * HD;
#pragma unroll
        for (int it = 0; it < 4; it++) {
            const int idx = (tid + it * 256) * 4;
            *(float4*)&Sp[idx] = *(const float4*)&spg[idx];
        }
        if (tid < HD) k1p[tid] = g_pk1[((size_t)bh * NCHUNK + c) * HD + tid];
    }
    __syncthreads();

    const int tx = tid & 15, ty = tid >> 4;

    {
        float acc[8][8];
#pragma unroll
        for (int i = 0; i < 8; i++)
#pragma unroll
            for (int j = 0; j < 8; j++) acc[i][j] = 0.f;
#pragma unroll 4
        for (int kk = 0; kk < HD; kk++) {
            float qf[8], kf[8];
            *(float4*)(qf)     = *(const float4*)&QsT[kk * SMS + ty * 8];
            *(float4*)(qf + 4) = *(const float4*)&QsT[kk * SMS + ty * 8 + 4];
            *(float4*)(kf)     = *(const float4*)&KsT[kk * SMS + tx * 8];
            *(float4*)(kf + 4) = *(const float4*)&KsT[kk * SMS + tx * 8 + 4];
#pragma unroll
            for (int i = 0; i < 8; i++)
#pragma unroll
                for (int j = 0; j < 8; j++)
                    acc[i][j] = fmaf(qf[i], kf[j], acc[i][j]);
        }
#pragma unroll
        for (int i = 0; i < 8; i++) {
            const int t = ty * 8 + i;
            float o[8];
#pragma unroll
            for (int j = 0; j < 8; j++) {
                const int tp = tx * 8 + j;
                o[j] = (tp <= t) ? acc[i][j] : 0.f;
            }
            *(float4*)&Am[t * SMS + tx * 8]     = *(float4*)o;
            *(float4*)&Am[t * SMS + tx * 8 + 4] = *(float4*)(o + 4);
        }
    }
    __syncthreads();

    if (tid < CHUNK) {
        const int t = tid;
        float s = 0.f;
#pragma unroll 8
        for (int d = 0; d < HD; d++) s = fmaf(QsT[d * SMS + t], k1p[d], s);
        for (int tp = 0; tp <= t; tp++) s += Am[t * SMS + tp];
        dens[t] = s;
    }
    __syncthreads();

    {
        float acc[8][4];
#pragma unroll
        for (int i = 0; i < 8; i++)
#pragma unroll
            for (int j = 0; j < 4; j++) acc[i][j] = 0.f;
#pragma unroll 4
        for (int tp = 0; tp < CHUNK; tp++) {
            float vf[4];
            *(float4*)vf = *(const float4*)&Vs[tp * HD + tx * 4];
#pragma unroll
            for (int i = 0; i < 8; i++) {
                const float a = Am[(ty * 8 + i) * SMS + tp];
#pragma unroll
                for (int j = 0; j < 4; j++) acc[i][j] = fmaf(a, vf[j], acc[i][j]);
            }
        }
#pragma unroll 4
        for (int d1 = 0; d1 < HD; d1++) {
            float vf[4];
            *(float4*)vf = *(const float4*)&Sp[d1 * HD + tx * 4];
#pragma unroll
            for (int i = 0; i < 8; i++) {
                const float a = QsT[d1 * SMS + ty * 8 + i];
#pragma unroll
                for (int j = 0; j < 4; j++) acc[i][j] = fmaf(a, vf[j], acc[i][j]);
            }
        }
#pragma unroll
        for (int i = 0; i < 8; i++) {
            const int t = ty * 8 + i;
            const float inv = 1.0f / dens[t];
            float4 o;
            o.x = acc[i][0] * inv;
            o.y = acc[i][1] * inv;
            o.z = acc[i][2] * inv;
            o.w = acc[i][3] * inv;
            *(float4*)(g_att + base + (size_t)t * DIMV + tx * 4) = o;
        }
    }
}

// ---------------------------------------------------------------------------
// Launch — pure kernel launches (no symbol queries, no sync, no alloc)
// ---------------------------------------------------------------------------
extern "C" void kernel_launch(void* const* d_in, const int* in_sizes, int n_in,
                              void* d_out, int out_size)
{
    const float* x  = (const float*)d_in[0];
    const float* Wq = (const float*)d_in[1];
    const float* bq = (const float*)d_in[2];
    const float* Wk = (const float*)d_in[3];
    const float* bk = (const float*)d_in[4];
    const float* Wv = (const float*)d_in[5];
    const float* bv = (const float*)d_in[6];
    const float* Wo = (const float*)d_in[7];
    const float* bo = (const float*)d_in[8];
    float* out = (float*)d_out;

    const int stats_smem = 2 * CHUNK * HD * (int)sizeof(float);              // 64 KB
    const int cout_smem  = (2 * HD * SMS + CHUNK * HD + HD * HD +
                            CHUNK * SMS + HD + CHUNK) * (int)sizeof(float);  // ~181 KB
    cudaFuncSetAttribute(qkv_mma_kernel,
                         cudaFuncAttributeMaxDynamicSharedMemorySize, GEMM_SMEM);
    cudaFuncSetAttribute(out_mma_kernel,
                         cudaFuncAttributeMaxDynamicSharedMemorySize, GEMM_SMEM);
    cudaFuncSetAttribute(chunk_stats_kernel,
                         cudaFuncAttributeMaxDynamicSharedMemorySize, stats_smem);
    cudaFuncSetAttribute(chunk_out_kernel,
                         cudaFuncAttributeMaxDynamicSharedMemorySize, cout_smem);

    // 1. split activations (x) and weights into tf32 hi/lo
    split_act_kernel<<<512, 256>>>(x);
    split_w_kernel<<<256, 256>>>(Wq, 0);
    split_w_kernel<<<256, 256>>>(Wk, 1);
    split_w_kernel<<<256, 256>>>(Wv, 2);
    split_w_kernel<<<256, 256>>>(Wo, 3);

    // 2. QKV projections (+exp for q,k)
    qkv_mma_kernel<<<dim3(NDIM / 128, M_ROWS / 128, 3), 256, GEMM_SMEM>>>(bq, bk, bv);

    // 3. chunked linear attention
    chunk_stats_kernel<<<dim3(NCHUNK, BHEADS), 256, stats_smem>>>();
    prefix_kernel<<<BHEADS, 256>>>();
    chunk_out_kernel<<<dim3(NCHUNK, BHEADS), 256, cout_smem>>>();

    // 4. split attention output, then output projection
    split_att_kernel<<<512, 256>>>();
    out_mma_kernel<<<dim3(NDIM / 128, M_ROWS / 128), 256, GEMM_SMEM>>>(bo, out);
}

// round 8
// speedup vs baseline: 1.6216x; 1.6216x over previous
#include <cuda_runtime.h>
#include <cuda_fp16.h>
#include <cstdint>

// Problem constants
#define S_LEN  2048
#define DIMV   1024
#define NHEAD  16
#define HD     64
#define BATCH  2
#define M_ROWS (BATCH * S_LEN)     // 4096
#define KDIM   1024
#define NDIM   1024
#define BHEADS (BATCH * NHEAD)     // 32
#define CHUNK  128
#define NCHUNK (S_LEN / CHUNK)     // 16

// ---------------------------------------------------------------------------
// Scratch (static device globals: allocation-free per harness rules)
// ---------------------------------------------------------------------------
__device__ float g_q[M_ROWS * DIMV];
__device__ float g_k[M_ROWS * DIMV];
__device__ float g_v[M_ROWS * DIMV];
__device__ float g_att[M_ROWS * DIMV];
__device__ float g_ckv[BHEADS * NCHUNK * HD * HD];
__device__ float g_ck1[BHEADS * NCHUNK * HD];
__device__ float g_pkv[BHEADS * NCHUNK * HD * HD];
__device__ float g_pk1[BHEADS * NCHUNK * HD];

#define SMS 132  // padded shared stride for the fp32 attention kernels

// ===========================================================================
// fp16-split GEMM (3-pass: ah*bh + ah*bl + al*bh), m16n8k16 HMMA.
// C[m,n] = sum_k A[m,k]*W[n,k] + bias[n], optional exp epilogue.
// CTA 128x128, 256 threads, 8 warps (2x4 grid, 64x32 warp tiles), BK=16.
// Smem: fp16 tiles Ah/Al/Bh/Bl, row stride 24 halves (12 words) --
// fragment LDS pattern (12g+t, +4) is a bank permutation: conflict-free.
// ===========================================================================
#define BK    16
#define NKST  (KDIM / BK)     // 64
#define RWRD  12              // words per smem row (8 data words + 4 pad)
#define TILW  (128 * RWRD)    // 1536 words per fp16 tile
#define AHW   0
#define ALW   TILW
#define BHW   (2 * TILW)
#define BLW   (3 * TILW)
#define STGW  (4 * TILW)      // 6144 words per stage
#define GEMM_SMEM (2 * STGW * 4)   // 49152 bytes

__device__ __forceinline__ uint32_t h2u(__half2 h) {
    return *reinterpret_cast<uint32_t*>(&h);
}

__device__ __forceinline__ void mma_f16(float* d, const uint32_t* a,
                                        uint32_t b0, uint32_t b1) {
    asm volatile(
        "mma.sync.aligned.m16n8k16.row.col.f32.f16.f16.f32 "
        "{%0,%1,%2,%3}, {%4,%5,%6,%7}, {%8,%9}, {%0,%1,%2,%3};"
        : "+f"(d[0]), "+f"(d[1]), "+f"(d[2]), "+f"(d[3])
        : "r"(a[0]), "r"(a[1]), "r"(a[2]), "r"(a[3]), "r"(b0), "r"(b1));
}

// 8 fp32 -> 4 fp16x2 hi + 4 fp16x2 lo (residual)
__device__ __forceinline__ void cvt8(float4 a, float4 b, uint4& hi, uint4& lo)
{
    __half2 h0 = __floats2half2_rn(a.x, a.y);
    __half2 h1 = __floats2half2_rn(a.z, a.w);
    __half2 h2 = __floats2half2_rn(b.x, b.y);
    __half2 h3 = __floats2half2_rn(b.z, b.w);
    float2 f0 = __half22float2(h0);
    float2 f1 = __half22float2(h1);
    float2 f2 = __half22float2(h2);
    float2 f3 = __half22float2(h3);
    __half2 l0 = __floats2half2_rn(a.x - f0.x, a.y - f0.y);
    __half2 l1 = __floats2half2_rn(a.z - f1.x, a.w - f1.y);
    __half2 l2 = __floats2half2_rn(b.x - f2.x, b.y - f2.y);
    __half2 l3 = __floats2half2_rn(b.z - f3.x, b.w - f3.y);
    hi.x = h2u(h0); hi.y = h2u(h1);
    hi.z = h2u(h2); hi.w = h2u(h3);
    lo.x = h2u(l0); lo.y = h2u(l1);
    lo.z = h2u(l2); lo.w = h2u(l3);
}

__device__ __forceinline__ void gemm_f16split(
    const float* __restrict__ A, const float* __restrict__ W,
    const float* __restrict__ bias, float* __restrict__ out, int doExp,
    int m0, int n0)
{
    extern __shared__ uint32_t su[];

    const int tid = threadIdx.x;
    const int lane = tid & 31, wid = tid >> 5;
    const int wm = wid >> 2, wn = wid & 3;       // 2 x 4 warp grid
    const int grp = lane >> 2, tig = lane & 3;
    const int r = tid >> 1, h = tid & 1;         // load coords: 2 thr/row

    const float* pA = A + (size_t)(m0 + r) * KDIM + h * 8;
    const float* pB = W + (size_t)(n0 + r) * KDIM + h * 8;
    const int stw = r * RWRD + h * 4;            // store word offset in tile

    float acc[4][4][4];
#pragma unroll
    for (int mt = 0; mt < 4; mt++)
#pragma unroll
        for (int nt = 0; nt < 4; nt++)
#pragma unroll
            for (int e = 0; e < 4; e++) acc[mt][nt][e] = 0.f;

    float4 ra0, ra1, rb0, rb1;

    // prologue: stage 0
    ra0 = *(const float4*)(pA);
    ra1 = *(const float4*)(pA + 4);
    rb0 = *(const float4*)(pB);
    rb1 = *(const float4*)(pB + 4);
    {
        uint32_t* d = su + stw;  // buffer 0
        uint4 hi, lo;
        cvt8(ra0, ra1, hi, lo);
        *(uint4*)(d + AHW) = hi;
        *(uint4*)(d + ALW) = lo;
        cvt8(rb0, rb1, hi, lo);
        *(uint4*)(d + BHW) = hi;
        *(uint4*)(d + BLW) = lo;
    }
    __syncthreads();

    for (int s = 0; s < NKST; s++) {
        const int nxt = s + 1;
        if (nxt < NKST) {
            const int k0 = nxt * BK;
            ra0 = *(const float4*)(pA + k0);
            ra1 = *(const float4*)(pA + k0 + 4);
            rb0 = *(const float4*)(pB + k0);
            rb1 = *(const float4*)(pB + k0 + 4);
        }

        // compute on buffer s&1 (one k16 step)
        {
            const uint32_t* bu = su + (s & 1) * STGW;
            uint32_t ah[4][4], al[4][4];
#pragma unroll
            for (int mt = 0; mt < 4; mt++) {
                const int ro = (wm * 64 + mt * 16 + grp) * RWRD;
                ah[mt][0] = bu[AHW + ro + tig];
                ah[mt][1] = bu[AHW + ro + 8 * RWRD + tig];
                ah[mt][2] = bu[AHW + ro + tig + 4];
                ah[mt][3] = bu[AHW + ro + 8 * RWRD + tig + 4];
                al[mt][0] = bu[ALW + ro + tig];
                al[mt][1] = bu[ALW + ro + 8 * RWRD + tig];
                al[mt][2] = bu[ALW + ro + tig + 4];
                al[mt][3] = bu[ALW + ro + 8 * RWRD + tig + 4];
            }
#pragma unroll
            for (int nt = 0; nt < 4; nt++) {
                const int ro = (wn * 32 + nt * 8 + grp) * RWRD;
                const uint32_t bh0 = bu[BHW + ro + tig];
                const uint32_t bh1 = bu[BHW + ro + tig + 4];
                const uint32_t bl0 = bu[BLW + ro + tig];
                const uint32_t bl1 = bu[BLW + ro + tig + 4];
#pragma unroll
                for (int mt = 0; mt < 4; mt++) {
                    mma_f16(acc[mt][nt], ah[mt], bh0, bh1);
                    mma_f16(acc[mt][nt], ah[mt], bl0, bl1);
                    mma_f16(acc[mt][nt], al[mt], bh0, bh1);
                }
            }
        }

        if (nxt < NKST) {
            uint32_t* d = su + (nxt & 1) * STGW + stw;
            uint4 hi, lo;
            cvt8(ra0, ra1, hi, lo);
            *(uint4*)(d + AHW) = hi;
            *(uint4*)(d + ALW) = lo;
            cvt8(rb0, rb1, hi, lo);
            *(uint4*)(d + BHW) = hi;
            *(uint4*)(d + BLW) = lo;
        }
        __syncthreads();
    }

    // epilogue: c0,c1 = (grp, 2tig..2tig+1); c2,c3 = (grp+8, same)
#pragma unroll
    for (int mt = 0; mt < 4; mt++) {
        const int rr = m0 + wm * 64 + mt * 16 + grp;
#pragma unroll
        for (int nt = 0; nt < 4; nt++) {
            const int cc = n0 + wn * 32 + nt * 8 + 2 * tig;
            const float bb0 = bias[cc], bb1 = bias[cc + 1];
            float v0 = acc[mt][nt][0] + bb0;
            float v1 = acc[mt][nt][1] + bb1;
            float v2 = acc[mt][nt][2] + bb0;
            float v3 = acc[mt][nt][3] + bb1;
            if (doExp) {
                v0 = expf(v0); v1 = expf(v1); v2 = expf(v2); v3 = expf(v3);
            }
            float2 p0; p0.x = v0; p0.y = v1;
            float2 p1; p1.x = v2; p1.y = v3;
            *(float2*)&out[(size_t)rr * NDIM + cc]       = p0;
            *(float2*)&out[(size_t)(rr + 8) * NDIM + cc] = p1;
        }
    }
}

__global__ void __launch_bounds__(256, 2) qkv_mma_kernel(
    const float* __restrict__ x,
    const float* __restrict__ Wq, const float* __restrict__ bq,
    const float* __restrict__ Wk, const float* __restrict__ bk,
    const float* __restrict__ Wv, const float* __restrict__ bv)
{
    const int z = blockIdx.z;
    const float* W    = (z == 0) ? Wq : ((z == 1) ? Wk : Wv);
    const float* bias = (z == 0) ? bq : ((z == 1) ? bk : bv);
    float* out        = (z == 0) ? g_q : ((z == 1) ? g_k : g_v);
    gemm_f16split(x, W, bias, out, z < 2, blockIdx.y * 128, blockIdx.x * 128);
}

__global__ void __launch_bounds__(256, 2) out_mma_kernel(
    const float* __restrict__ Wo, const float* __restrict__ bo,
    float* __restrict__ out)
{
    gemm_f16split(g_att, Wo, bo, out, 0, blockIdx.y * 128, blockIdx.x * 128);
}

// ---------------------------------------------------------------------------
// Chunk stats: per (head, chunk) compute sum_t k_t v_t^T (64x64) and sum_t k_t
// ---------------------------------------------------------------------------
__global__ void __launch_bounds__(256) chunk_stats_kernel()
{
    extern __shared__ __align__(16) float sm[];
    float* Ks = sm;
    float* Vs = sm + CHUNK * HD;
    const int bh = blockIdx.y, c = blockIdx.x;
    const int b = bh >> 4, hh = bh & 15;
    const int tid = threadIdx.x;
    const size_t base = ((size_t)(b * S_LEN + c * CHUNK)) * DIMV + hh * HD;

#pragma unroll
    for (int it = 0; it < 8; it++) {
        const int idx = tid + it * 256;
        const int t = idx >> 4, dv = idx & 15;
        *(float4*)&Ks[t * HD + dv * 4] =
            *(const float4*)(g_k + base + (size_t)t * DIMV + dv * 4);
        *(float4*)&Vs[t * HD + dv * 4] =
            *(const float4*)(g_v + base + (size_t)t * DIMV + dv * 4);
    }
    __syncthreads();

    const int tx = tid & 15, ty = tid >> 4;
    float acc[4][4];
#pragma unroll
    for (int i = 0; i < 4; i++)
#pragma unroll
        for (int j = 0; j < 4; j++) acc[i][j] = 0.f;

#pragma unroll 4
    for (int t = 0; t < CHUNK; t++) {
        float kf[4], vf[4];
        *(float4*)kf = *(const float4*)&Ks[t * HD + ty * 4];
        *(float4*)vf = *(const float4*)&Vs[t * HD + tx * 4];
#pragma unroll
        for (int i = 0; i < 4; i++)
#pragma unroll
            for (int j = 0; j < 4; j++)
                acc[i][j] = fmaf(kf[i], vf[j], acc[i][j]);
    }

    float* okv = g_ckv + ((size_t)bh * NCHUNK + c) * HD * HD;
#pragma unroll
    for (int i = 0; i < 4; i++)
        *(float4*)&okv[(ty * 4 + i) * HD + tx * 4] = *(float4*)acc[i];

    if (tid < HD) {
        float s = 0.f;
#pragma unroll 8
        for (int t = 0; t < CHUNK; t++) s += Ks[t * HD + tid];
        g_ck1[((size_t)bh * NCHUNK + c) * HD + tid] = s;
    }
}

// ---------------------------------------------------------------------------
// Exclusive prefix over the 16 chunk states per head
// ---------------------------------------------------------------------------
__global__ void __launch_bounds__(256) prefix_kernel()
{
    const int bh = blockIdx.x, tid = threadIdx.x;
    for (int e = tid; e < HD * HD; e += 256) {
        float run = 0.f;
#pragma unroll
        for (int c = 0; c < NCHUNK; c++) {
            const size_t off = ((size_t)bh * NCHUNK + c) * HD * HD + e;
            g_pkv[off] = run;
            run += g_ckv[off];
        }
    }
    if (tid < HD) {
        float run = 0.f;
#pragma unroll
        for (int c = 0; c < NCHUNK; c++) {
            const size_t off = ((size_t)bh * NCHUNK + c) * HD + tid;
            g_pk1[off] = run;
            run += g_ck1[off];
        }
    }
}

// ---------------------------------------------------------------------------
// Chunk output: out_t = (q_t @ KVprev + sum_{t'<=t} (q_t.k_t') v_t') / den_t
// ---------------------------------------------------------------------------
__global__ void __launch_bounds__(256) chunk_out_kernel()
{
    extern __shared__ __align__(16) float sm[];
    float* QsT  = sm;
    float* KsT  = QsT + HD * SMS;
    float* Vs   = KsT + HD * SMS;
    float* Sp   = Vs + CHUNK * HD;
    float* Am   = Sp + HD * HD;
    float* k1p  = Am + CHUNK * SMS;
    float* dens = k1p + HD;

    const int bh = blockIdx.y, c = blockIdx.x;
    const int b = bh >> 4, hh = bh & 15;
    const int tid = threadIdx.x;
    const size_t base = ((size_t)(b * S_LEN + c * CHUNK)) * DIMV + hh * HD;

#pragma unroll
    for (int it = 0; it < 8; it++) {
        const int idx = tid + it * 256;
        const int t = idx >> 4, dv = idx & 15;
        float4 q4 = *(const float4*)(g_q + base + (size_t)t * DIMV + dv * 4);
        float4 k4 = *(const float4*)(g_k + base + (size_t)t * DIMV + dv * 4);
        float4 v4 = *(const float4*)(g_v + base + (size_t)t * DIMV + dv * 4);
        QsT[(dv * 4 + 0) * SMS + t] = q4.x;
        QsT[(dv * 4 + 1) * SMS + t] = q4.y;
        QsT[(dv * 4 + 2) * SMS + t] = q4.z;
        QsT[(dv * 4 + 3) * SMS + t] = q4.w;
        KsT[(dv * 4 + 0) * SMS + t] = k4.x;
        KsT[(dv * 4 + 1) * SMS + t] = k4.y;
        KsT[(dv * 4 + 2) * SMS + t] = k4.z;
        KsT[(dv * 4 + 3) * SMS + t] = k4.w;
        *(float4*)&Vs[t * HD + dv * 4] = v4;
    }
    {
        const float* spg = g_pkv + ((size_t)bh * NCHUNK + c) * HD * HD;
#pragma unroll
        for (int it = 0; it < 4; it++) {
            const int idx = (tid + it * 256) * 4;
            *(float4*)&Sp[idx] = *(const float4*)&spg[idx];
        }
        if (tid < HD) k1p[tid] = g_pk1[((size_t)bh * NCHUNK + c) * HD + tid];
    }
    __syncthreads();

    const int tx = tid & 15, ty = tid >> 4;

    {
        float acc[8][8];
#pragma unroll
        for (int i = 0; i < 8; i++)
#pragma unroll
            for (int j = 0; j < 8; j++) acc[i][j] = 0.f;
#pragma unroll 4
        for (int kk = 0; kk < HD; kk++) {
            float qf[8], kf[8];
            *(float4*)(qf)     = *(const float4*)&QsT[kk * SMS + ty * 8];
            *(float4*)(qf + 4) = *(const float4*)&QsT[kk * SMS + ty * 8 + 4];
            *(float4*)(kf)     = *(const float4*)&KsT[kk * SMS + tx * 8];
            *(float4*)(kf + 4) = *(const float4*)&KsT[kk * SMS + tx * 8 + 4];
#pragma unroll
            for (int i = 0; i < 8; i++)
#pragma unroll
                for (int j = 0; j < 8; j++)
                    acc[i][j] = fmaf(qf[i], kf[j], acc[i][j]);
        }
#pragma unroll
        for (int i = 0; i < 8; i++) {
            const int t = ty * 8 + i;
            float o[8];
#pragma unroll
            for (int j = 0; j < 8; j++) {
                const int tp = tx * 8 + j;
                o[j] = (tp <= t) ? acc[i][j] : 0.f;
            }
            *(float4*)&Am[t * SMS + tx * 8]     = *(float4*)o;
            *(float4*)&Am[t * SMS + tx * 8 + 4] = *(float4*)(o + 4);
        }
    }
    __syncthreads();

    if (tid < CHUNK) {
        const int t = tid;
        float s = 0.f;
#pragma unroll 8
        for (int d = 0; d < HD; d++) s = fmaf(QsT[d * SMS + t], k1p[d], s);
        for (int tp = 0; tp <= t; tp++) s += Am[t * SMS + tp];
        dens[t] = s;
    }
    __syncthreads();

    {
        float acc[8][4];
#pragma unroll
        for (int i = 0; i < 8; i++)
#pragma unroll
            for (int j = 0; j < 4; j++) acc[i][j] = 0.f;
#pragma unroll 4
        for (int tp = 0; tp < CHUNK; tp++) {
            float vf[4];
            *(float4*)vf = *(const float4*)&Vs[tp * HD + tx * 4];
#pragma unroll
            for (int i = 0; i < 8; i++) {
                const float a = Am[(ty * 8 + i) * SMS + tp];
#pragma unroll
                for (int j = 0; j < 4; j++) acc[i][j] = fmaf(a, vf[j], acc[i][j]);
            }
        }
#pragma unroll 4
        for (int d1 = 0; d1 < HD; d1++) {
            float vf[4];
            *(float4*)vf = *(const float4*)&Sp[d1 * HD + tx * 4];
#pragma unroll
            for (int i = 0; i < 8; i++) {
                const float a = QsT[d1 * SMS + ty * 8 + i];
#pragma unroll
                for (int j = 0; j < 4; j++) acc[i][j] = fmaf(a, vf[j], acc[i][j]);
            }
        }
#pragma unroll
        for (int i = 0; i < 8; i++) {
            const int t = ty * 8 + i;
            const float inv = 1.0f / dens[t];
            float4 o;
            o.x = acc[i][0] * inv;
            o.y = acc[i][1] * inv;
            o.z = acc[i][2] * inv;
            o.w = acc[i][3] * inv;
            *(float4*)(g_att + base + (size_t)t * DIMV + tx * 4) = o;
        }
    }
}

// ---------------------------------------------------------------------------
// Launch
// ---------------------------------------------------------------------------
extern "C" void kernel_launch(void* const* d_in, const int* in_sizes, int n_in,
                              void* d_out, int out_size)
{
    const float* x  = (const float*)d_in[0];
    const float* Wq = (const float*)d_in[1];
    const float* bq = (const float*)d_in[2];
    const float* Wk = (const float*)d_in[3];
    const float* bk = (const float*)d_in[4];
    const float* Wv = (const float*)d_in[5];
    const float* bv = (const float*)d_in[6];
    const float* Wo = (const float*)d_in[7];
    const float* bo = (const float*)d_in[8];
    float* out = (float*)d_out;

    const int stats_smem = 2 * CHUNK * HD * (int)sizeof(float);              // 64 KB
    const int cout_smem  = (2 * HD * SMS + CHUNK * HD + HD * HD +
                            CHUNK * SMS + HD + CHUNK) * (int)sizeof(float);  // ~181 KB
    cudaFuncSetAttribute(qkv_mma_kernel,
                         cudaFuncAttributeMaxDynamicSharedMemorySize, GEMM_SMEM);
    cudaFuncSetAttribute(out_mma_kernel,
                         cudaFuncAttributeMaxDynamicSharedMemorySize, GEMM_SMEM);
    cudaFuncSetAttribute(chunk_stats_kernel,
                         cudaFuncAttributeMaxDynamicSharedMemorySize, stats_smem);
    cudaFuncSetAttribute(chunk_out_kernel,
                         cudaFuncAttributeMaxDynamicSharedMemorySize, cout_smem);

    qkv_mma_kernel<<<dim3(NDIM / 128, M_ROWS / 128, 3), 256, GEMM_SMEM>>>(
        x, Wq, bq, Wk, bk, Wv, bv);
    chunk_stats_kernel<<<dim3(NCHUNK, BHEADS), 256, stats_smem>>>();
    prefix_kernel<<<BHEADS, 256>>>();
    chunk_out_kernel<<<dim3(NCHUNK, BHEADS), 256, cout_smem>>>();
    out_mma_kernel<<<dim3(NDIM / 128, M_ROWS / 128), 256, GEMM_SMEM>>>(Wo, bo, out);
}

// round 11
// speedup vs baseline: 1.6670x; 1.0280x over previous
#include <cuda_runtime.h>
#include <cuda_fp16.h>
#include <cstdint>

// Problem constants
#define S_LEN  2048
#define DIMV   1024
#define NHEAD  16
#define HD     64
#define BATCH  2
#define M_ROWS (BATCH * S_LEN)     // 4096
#define KDIM   1024
#define NDIM   1024
#define BHEADS (BATCH * NHEAD)     // 32
#define CHUNK  128
#define NCHUNK (S_LEN / CHUNK)     // 16

// ---------------------------------------------------------------------------
// Scratch (static device globals: allocation-free per harness rules)
// ---------------------------------------------------------------------------
__device__ float g_q[M_ROWS * DIMV];
__device__ float g_k[M_ROWS * DIMV];
__device__ float g_v[M_ROWS * DIMV];
__device__ float g_att[M_ROWS * DIMV];
__device__ float g_ckv[BHEADS * NCHUNK * HD * HD];
__device__ float g_ck1[BHEADS * NCHUNK * HD];
__device__ float g_pkv[BHEADS * NCHUNK * HD * HD];
__device__ float g_pk1[BHEADS * NCHUNK * HD];
__device__ float g_den[BHEADS * NCHUNK * CHUNK];

#define SMS 132  // padded shared stride for the fp32 attention kernels

// ===========================================================================
// fp16-split GEMM (3-pass: ah*bh + ah*bl + al*bh), m16n8k16 HMMA.
// CTA 128(M)x64(N), 256 threads, 8 warps in 4x2 grid, 32x32 warp tiles.
// acc = 32 regs/thread -> ~105 total: fits 128-reg cap at 2 CTAs/SM, NO SPILLS.
// ===========================================================================
#define BK    16
#define NKST  (KDIM / BK)     // 64
#define RWRD  12              // words per smem row
#define TAW   (128 * RWRD)    // 1536 words: A tile (hi or lo)
#define TBW   (64 * RWRD)     // 768  words: B tile (hi or lo)
#define AHW   0
#define ALW   TAW
#define BHW   (2 * TAW)
#define BLW   (2 * TAW + TBW)
#define STGW  (2 * TAW + 2 * TBW)   // 4608 words per stage
#define GEMM_SMEM (2 * STGW * 4)    // 36864 bytes

__device__ __forceinline__ uint32_t h2u(__half2 h) {
    return *reinterpret_cast<uint32_t*>(&h);
}

__device__ __forceinline__ void mma_f16(float* d, const uint32_t* a,
                                        uint32_t b0, uint32_t b1) {
    asm volatile(
        "mma.sync.aligned.m16n8k16.row.col.f32.f16.f16.f32 "
        "{%0,%1,%2,%3}, {%4,%5,%6,%7}, {%8,%9}, {%0,%1,%2,%3};"
        : "+f"(d[0]), "+f"(d[1]), "+f"(d[2]), "+f"(d[3])
        : "r"(a[0]), "r"(a[1]), "r"(a[2]), "r"(a[3]), "r"(b0), "r"(b1));
}

__device__ __forceinline__ void cvt8(float4 a, float4 b, uint4& hi, uint4& lo)
{
    __half2 h0 = __floats2half2_rn(a.x, a.y);
    __half2 h1 = __floats2half2_rn(a.z, a.w);
    __half2 h2 = __floats2half2_rn(b.x, b.y);
    __half2 h3 = __floats2half2_rn(b.z, b.w);
    float2 f0 = __half22float2(h0);
    float2 f1 = __half22float2(h1);
    float2 f2 = __half22float2(h2);
    float2 f3 = __half22float2(h3);
    __half2 l0 = __floats2half2_rn(a.x - f0.x, a.y - f0.y);
    __half2 l1 = __floats2half2_rn(a.z - f1.x, a.w - f1.y);
    __half2 l2 = __floats2half2_rn(b.x - f2.x, b.y - f2.y);
    __half2 l3 = __floats2half2_rn(b.z - f3.x, b.w - f3.y);
    hi.x = h2u(h0); hi.y = h2u(h1); hi.z = h2u(h2); hi.w = h2u(h3);
    lo.x = h2u(l0); lo.y = h2u(l1); lo.z = h2u(l2); lo.w = h2u(l3);
}

__device__ __forceinline__ void cvt4(float4 a, uint2& hi, uint2& lo)
{
    __half2 h0 = __floats2half2_rn(a.x, a.y);
    __half2 h1 = __floats2half2_rn(a.z, a.w);
    float2 f0 = __half22float2(h0);
    float2 f1 = __half22float2(h1);
    __half2 l0 = __floats2half2_rn(a.x - f0.x, a.y - f0.y);
    __half2 l1 = __floats2half2_rn(a.z - f1.x, a.w - f1.y);
    hi.x = h2u(h0); hi.y = h2u(h1);
    lo.x = h2u(l0); lo.y = h2u(l1);
}

__device__ __forceinline__ void gemm_f16split(
    const float* __restrict__ A, const float* __restrict__ W,
    const float* __restrict__ bias, float* __restrict__ out, int doExp,
    int m0, int n0)
{
    extern __shared__ uint32_t su[];

    const int tid = threadIdx.x;
    const int lane = tid & 31, wid = tid >> 5;
    const int wm = wid >> 1, wn = wid & 1;       // 4 x 2 warp grid
    const int grp = lane >> 2, tig = lane & 3;

    const int rA = tid >> 1, hA = tid & 1;
    const float* pA = A + (size_t)(m0 + rA) * KDIM + hA * 8;
    const int stwA = rA * RWRD + hA * 4;
    const int rB = tid >> 2, qB = tid & 3;
    const float* pB = W + (size_t)(n0 + rB) * KDIM + qB * 4;
    const int stwB = rB * RWRD + qB * 2;

    float acc[2][4][4];
#pragma unroll
    for (int mt = 0; mt < 2; mt++)
#pragma unroll
        for (int nt = 0; nt < 4; nt++)
#pragma unroll
            for (int e = 0; e < 4; e++) acc[mt][nt][e] = 0.f;

    float4 ra0, ra1, rb;

    ra0 = *(const float4*)(pA);
    ra1 = *(const float4*)(pA + 4);
    rb  = *(const float4*)(pB);
    {
        uint32_t* d = su;
        uint4 hi, lo;
        cvt8(ra0, ra1, hi, lo);
        *(uint4*)(d + AHW + stwA) = hi;
        *(uint4*)(d + ALW + stwA) = lo;
        uint2 hb, lb;
        cvt4(rb, hb, lb);
        *(uint2*)(d + BHW + stwB) = hb;
        *(uint2*)(d + BLW + stwB) = lb;
    }
    __syncthreads();

    for (int s = 0; s < NKST; s++) {
        const int nxt = s + 1;
        if (nxt < NKST) {
            const int k0 = nxt * BK;
            ra0 = *(const float4*)(pA + k0);
            ra1 = *(const float4*)(pA + k0 + 4);
            rb  = *(const float4*)(pB + k0);
        }

        {
            const uint32_t* bu = su + (s & 1) * STGW;
            uint32_t ah[2][4], al[2][4];
#pragma unroll
            for (int mt = 0; mt < 2; mt++) {
                const int ro = (wm * 32 + mt * 16 + grp) * RWRD;
                ah[mt][0] = bu[AHW + ro + tig];
                ah[mt][1] = bu[AHW + ro + 8 * RWRD + tig];
                ah[mt][2] = bu[AHW + ro + tig + 4];
                ah[mt][3] = bu[AHW + ro + 8 * RWRD + tig + 4];
                al[mt][0] = bu[ALW + ro + tig];
                al[mt][1] = bu[ALW + ro + 8 * RWRD + tig];
                al[mt][2] = bu[ALW + ro + tig + 4];
                al[mt][3] = bu[ALW + ro + 8 * RWRD + tig + 4];
            }
#pragma unroll
            for (int nt = 0; nt < 4; nt++) {
                const int ro = (wn * 32 + nt * 8 + grp) * RWRD;
                const uint32_t bh0 = bu[BHW + ro + tig];
                const uint32_t bh1 = bu[BHW + ro + tig + 4];
                const uint32_t bl0 = bu[BLW + ro + tig];
                const uint32_t bl1 = bu[BLW + ro + tig + 4];
#pragma unroll
                for (int mt = 0; mt < 2; mt++) {
                    mma_f16(acc[mt][nt], ah[mt], bh0, bh1);
                    mma_f16(acc[mt][nt], ah[mt], bl0, bl1);
                    mma_f16(acc[mt][nt], al[mt], bh0, bh1);
                }
            }
        }

        if (nxt < NKST) {
            uint32_t* d = su + (nxt & 1) * STGW;
            uint4 hi, lo;
            cvt8(ra0, ra1, hi, lo);
            *(uint4*)(d + AHW + stwA) = hi;
            *(uint4*)(d + ALW + stwA) = lo;
            uint2 hb, lb;
            cvt4(rb, hb, lb);
            *(uint2*)(d + BHW + stwB) = hb;
            *(uint2*)(d + BLW + stwB) = lb;
        }
        __syncthreads();
    }

#pragma unroll
    for (int mt = 0; mt < 2; mt++) {
        const int rr = m0 + wm * 32 + mt * 16 + grp;
#pragma unroll
        for (int nt = 0; nt < 4; nt++) {
            const int cc = n0 + wn * 32 + nt * 8 + 2 * tig;
            const float bb0 = bias[cc], bb1 = bias[cc + 1];
            float v0 = acc[mt][nt][0] + bb0;
            float v1 = acc[mt][nt][1] + bb1;
            float v2 = acc[mt][nt][2] + bb0;
            float v3 = acc[mt][nt][3] + bb1;
            if (doExp) {
                v0 = expf(v0); v1 = expf(v1); v2 = expf(v2); v3 = expf(v3);
            }
            float2 p0; p0.x = v0; p0.y = v1;
            float2 p1; p1.x = v2; p1.y = v3;
            *(float2*)&out[(size_t)rr * NDIM + cc]       = p0;
            *(float2*)&out[(size_t)(rr + 8) * NDIM + cc] = p1;
        }
    }
}

__global__ void __launch_bounds__(256, 2) qkv_mma_kernel(
    const float* __restrict__ x,
    const float* __restrict__ Wq, const float* __restrict__ bq,
    const float* __restrict__ Wk, const float* __restrict__ bk,
    const float* __restrict__ Wv, const float* __restrict__ bv)
{
    const int z = blockIdx.z;
    const float* W    = (z == 0) ? Wq : ((z == 1) ? Wk : Wv);
    const float* bias = (z == 0) ? bq : ((z == 1) ? bk : bv);
    float* out        = (z == 0) ? g_q : ((z == 1) ? g_k : g_v);
    gemm_f16split(x, W, bias, out, z < 2, blockIdx.y * 128, blockIdx.x * 64);
}

__global__ void __launch_bounds__(256, 2) out_mma_kernel(
    const float* __restrict__ Wo, const float* __restrict__ bo,
    float* __restrict__ out)
{
    gemm_f16split(g_att, Wo, bo, out, 0, blockIdx.y * 128, blockIdx.x * 64);
}

// ---------------------------------------------------------------------------
// Chunk stats: per (head, chunk) compute sum_t k_t v_t^T (64x64) and sum_t k_t
// ---------------------------------------------------------------------------
__global__ void __launch_bounds__(256) chunk_stats_kernel()
{
    extern __shared__ __align__(16) float sm[];
    float* Ks = sm;
    float* Vs = sm + CHUNK * HD;
    const int bh = blockIdx.y, c = blockIdx.x;
    const int b = bh >> 4, hh = bh & 15;
    const int tid = threadIdx.x;
    const size_t base = ((size_t)(b * S_LEN + c * CHUNK)) * DIMV + hh * HD;

#pragma unroll
    for (int it = 0; it < 8; it++) {
        const int idx = tid + it * 256;
        const int t = idx >> 4, dv = idx & 15;
        *(float4*)&Ks[t * HD + dv * 4] =
            *(const float4*)(g_k + base + (size_t)t * DIMV + dv * 4);
        *(float4*)&Vs[t * HD + dv * 4] =
            *(const float4*)(g_v + base + (size_t)t * DIMV + dv * 4);
    }
    __syncthreads();

    const int tx = tid & 15, ty = tid >> 4;
    float acc[4][4];
#pragma unroll
    for (int i = 0; i < 4; i++)
#pragma unroll
        for (int j = 0; j < 4; j++) acc[i][j] = 0.f;

#pragma unroll 4
    for (int t = 0; t < CHUNK; t++) {
        float kf[4], vf[4];
        *(float4*)kf = *(const float4*)&Ks[t * HD + ty * 4];
        *(float4*)vf = *(const float4*)&Vs[t * HD + tx * 4];
#pragma unroll
        for (int i = 0; i < 4; i++)
#pragma unroll
            for (int j = 0; j < 4; j++)
                acc[i][j] = fmaf(kf[i], vf[j], acc[i][j]);
    }

    float* okv = g_ckv + ((size_t)bh * NCHUNK + c) * HD * HD;
#pragma unroll
    for (int i = 0; i < 4; i++)
        *(float4*)&okv[(ty * 4 + i) * HD + tx * 4] = *(float4*)acc[i];

    if (tid < HD) {
        float s = 0.f;
#pragma unroll 8
        for (int t = 0; t < CHUNK; t++) s += Ks[t * HD + tid];
        g_ck1[((size_t)bh * NCHUNK + c) * HD + tid] = s;
    }
}

// ---------------------------------------------------------------------------
// Exclusive prefix over the 16 chunk states per head
// ---------------------------------------------------------------------------
__global__ void __launch_bounds__(256) prefix_kernel()
{
    const int bh = blockIdx.x, tid = threadIdx.x;
    for (int e = tid; e < HD * HD; e += 256) {
        float run = 0.f;
#pragma unroll
        for (int c = 0; c < NCHUNK; c++) {
            const size_t off = ((size_t)bh * NCHUNK + c) * HD * HD + e;
            g_pkv[off] = run;
            run += g_ckv[off];
        }
    }
    if (tid < HD) {
        float run = 0.f;
#pragma unroll
        for (int c = 0; c < NCHUNK; c++) {
            const size_t off = ((size_t)bh * NCHUNK + c) * HD + tid;
            g_pk1[off] = run;
            run += g_ck1[off];
        }
    }
}

// ---------------------------------------------------------------------------
// Chunk partial (inter-chunk): g_att = Q @ Sp (partial), g_den = q . k1prefix
// smem ~51 KB -> 4 CTAs/SM.
// ---------------------------------------------------------------------------
#define QS   68                       // Q row stride (words)
#define PART_SMEM ((CHUNK * QS + HD * QS + HD) * 4)   // 52480 bytes

__global__ void __launch_bounds__(256) chunk_partial_kernel()
{
    extern __shared__ __align__(16) float sm[];
    float* Qs  = sm;                  // [128][68]
    float* Sps = sm + CHUNK * QS;     // [64][68]
    float* k1s = Sps + HD * QS;       // [64]

    const int bh = blockIdx.y, c = blockIdx.x;
    const int b = bh >> 4, hh = bh & 15;
    const int tid = threadIdx.x;
    const size_t base = ((size_t)(b * S_LEN + c * CHUNK)) * DIMV + hh * HD;
    const float* spg = g_pkv + ((size_t)bh * NCHUNK + c) * HD * HD;

#pragma unroll
    for (int it = 0; it < 8; it++) {
        const int idx = tid + it * 256;      // 0..2047 float4s
        const int t = idx >> 4, dv = idx & 15;
        *(float4*)&Qs[t * QS + dv * 4] =
            *(const float4*)(g_q + base + (size_t)t * DIMV + dv * 4);
    }
#pragma unroll
    for (int it = 0; it < 4; it++) {
        const int idx = tid + it * 256;      // 0..1023 float4s
        const int d1 = idx >> 4, dv = idx & 15;
        *(float4*)&Sps[d1 * QS + dv * 4] = *(const float4*)(spg + d1 * HD + dv * 4);
    }
    if (tid < HD) k1s[tid] = g_pk1[((size_t)bh * NCHUNK + c) * HD + tid];
    __syncthreads();

    const int tx = tid & 15, ty = tid >> 4;
    float acc[8][4];
#pragma unroll
    for (int i = 0; i < 8; i++)
#pragma unroll
        for (int j = 0; j < 4; j++) acc[i][j] = 0.f;

#pragma unroll 4
    for (int d1 = 0; d1 < HD; d1++) {
        float vf[4];
        *(float4*)vf = *(const float4*)&Sps[d1 * QS + tx * 4];
#pragma unroll
        for (int i = 0; i < 8; i++) {
            const float a = Qs[(ty * 8 + i) * QS + d1];
#pragma unroll
            for (int j = 0; j < 4; j++) acc[i][j] = fmaf(a, vf[j], acc[i][j]);
        }
    }

#pragma unroll
    for (int i = 0; i < 8; i++) {
        const int t = ty * 8 + i;
        *(float4*)(g_att + base + (size_t)t * DIMV + tx * 4) = *(float4*)acc[i];
    }

    if (tid < CHUNK) {
        float s = 0.f;
#pragma unroll 8
        for (int d = 0; d < HD; d++) s = fmaf(Qs[tid * QS + d], k1s[d], s);
        g_den[((size_t)bh * NCHUNK + c) * CHUNK + tid] = s;
    }
}

// ---------------------------------------------------------------------------
// Chunk output (intra-chunk): A = QK^T masked; out = (partial + A@V)/den.
// Am (128x132) OVERLAYS the dead QsT+KsT region after phase 2.
// smem 98 KB -> 2 CTAs/SM (regs <= 128 via launch_bounds(256,2)).
// ---------------------------------------------------------------------------
#define COUT_SMEM ((2 * HD * SMS + CHUNK * HD) * 4)   // 100352 bytes

__global__ void __launch_bounds__(256, 2) chunk_out_kernel()
{
    extern __shared__ __align__(16) float sm[];
    float* QsT = sm;                   // [64][132]
    float* KsT = sm + HD * SMS;        // [64][132]
    float* Am  = sm;                   // overlays QsT+KsT after phase 2: [128][132]
    float* Vs  = sm + 2 * HD * SMS;    // [128][64]
    __shared__ float dens[CHUNK];

    const int bh = blockIdx.y, c = blockIdx.x;
    const int b = bh >> 4, hh = bh & 15;
    const int tid = threadIdx.x;
    const size_t base = ((size_t)(b * S_LEN + c * CHUNK)) * DIMV + hh * HD;

#pragma unroll
    for (int it = 0; it < 8; it++) {
        const int idx = tid + it * 256;
        const int t = idx >> 4, dv = idx & 15;
        float4 q4 = *(const float4*)(g_q + base + (size_t)t * DIMV + dv * 4);
        float4 k4 = *(const float4*)(g_k + base + (size_t)t * DIMV + dv * 4);
        float4 v4 = *(const float4*)(g_v + base + (size_t)t * DIMV + dv * 4);
        QsT[(dv * 4 + 0) * SMS + t] = q4.x;
        QsT[(dv * 4 + 1) * SMS + t] = q4.y;
        QsT[(dv * 4 + 2) * SMS + t] = q4.z;
        QsT[(dv * 4 + 3) * SMS + t] = q4.w;
        KsT[(dv * 4 + 0) * SMS + t] = k4.x;
        KsT[(dv * 4 + 1) * SMS + t] = k4.y;
        KsT[(dv * 4 + 2) * SMS + t] = k4.z;
        KsT[(dv * 4 + 3) * SMS + t] = k4.w;
        *(float4*)&Vs[t * HD + dv * 4] = v4;
    }
    __syncthreads();

    const int tx = tid & 15, ty = tid >> 4;

    // phase 2: A = Q K^T into registers
    float acc[8][8];
#pragma unroll
    for (int i = 0; i < 8; i++)
#pragma unroll
        for (int j = 0; j < 8; j++) acc[i][j] = 0.f;
#pragma unroll 4
    for (int kk = 0; kk < HD; kk++) {
        float qf[8], kf[8];
        *(float4*)(qf)     = *(const float4*)&QsT[kk * SMS + ty * 8];
        *(float4*)(qf + 4) = *(const float4*)&QsT[kk * SMS + ty * 8 + 4];
        *(float4*)(kf)     = *(const float4*)&KsT[kk * SMS + tx * 8];
        *(float4*)(kf + 4) = *(const float4*)&KsT[kk * SMS + tx * 8 + 4];
#pragma unroll
        for (int i = 0; i < 8; i++)
#pragma unroll
            for (int j = 0; j < 8; j++)
                acc[i][j] = fmaf(qf[i], kf[j], acc[i][j]);
    }
    __syncthreads();   // all QsT/KsT reads done before Am overlays them

    // write masked Am over the QsT+KsT region
#pragma unroll
    for (int i = 0; i < 8; i++) {
        const int t = ty * 8 + i;
        float o[8];
#pragma unroll
        for (int j = 0; j < 8; j++) {
            const int tp = tx * 8 + j;
            o[j] = (tp <= t) ? acc[i][j] : 0.f;
        }
        *(float4*)&Am[t * SMS + tx * 8]     = *(float4*)o;
        *(float4*)&Am[t * SMS + tx * 8 + 4] = *(float4*)(o + 4);
    }
    __syncthreads();

    // denominator: g_den partial + row sum of masked Am (t-shifted, bank-free)
    if (tid < CHUNK) {
        float s = g_den[((size_t)bh * NCHUNK + c) * CHUNK + tid];
#pragma unroll 8
        for (int tp0 = 0; tp0 < CHUNK; tp0++) {
            const int tp = (tp0 + tid) & (CHUNK - 1);
            s += Am[tid * SMS + tp];
        }
        dens[tid] = 1.0f / s;
    }
    __syncthreads();

    // phase 3: out = (partial + Am @ V) * inv_den
    float acc2[8][4];
#pragma unroll
    for (int i = 0; i < 8; i++)
#pragma unroll
        for (int j = 0; j < 4; j++) acc2[i][j] = 0.f;
#pragma unroll 4
    for (int tp = 0; tp < CHUNK; tp++) {
        float vf[4];
        *(float4*)vf = *(const float4*)&Vs[tp * HD + tx * 4];
#pragma unroll
        for (int i = 0; i < 8; i++) {
            const float a = Am[(ty * 8 + i) * SMS + tp];
#pragma unroll
            for (int j = 0; j < 4; j++) acc2[i][j] = fmaf(a, vf[j], acc2[i][j]);
        }
    }
#pragma unroll
    for (int i = 0; i < 8; i++) {
        const int t = ty * 8 + i;
        const float inv = dens[t];
        float4 p = *(const float4*)(g_att + base + (size_t)t * DIMV + tx * 4);
        float4 o;
        o.x = (acc2[i][0] + p.x) * inv;
        o.y = (acc2[i][1] + p.y) * inv;
        o.z = (acc2[i][2] + p.z) * inv;
        o.w = (acc2[i][3] + p.w) * inv;
        *(float4*)(g_att + base + (size_t)t * DIMV + tx * 4) = o;
    }
}

// ---------------------------------------------------------------------------
// Launch
// ---------------------------------------------------------------------------
extern "C" void kernel_launch(void* const* d_in, const int* in_sizes, int n_in,
                              void* d_out, int out_size)
{
    const float* x  = (const float*)d_in[0];
    const float* Wq = (const float*)d_in[1];
    const float* bq = (const float*)d_in[2];
    const float* Wk = (const float*)d_in[3];
    const float* bk = (const float*)d_in[4];
    const float* Wv = (const float*)d_in[5];
    const float* bv = (const float*)d_in[6];
    const float* Wo = (const float*)d_in[7];
    const float* bo = (const float*)d_in[8];
    float* out = (float*)d_out;

    const int stats_smem = 2 * CHUNK * HD * (int)sizeof(float);   // 64 KB
    cudaFuncSetAttribute(qkv_mma_kernel,
                         cudaFuncAttributeMaxDynamicSharedMemorySize, GEMM_SMEM);
    cudaFuncSetAttribute(out_mma_kernel,
                         cudaFuncAttributeMaxDynamicSharedMemorySize, GEMM_SMEM);
    cudaFuncSetAttribute(chunk_stats_kernel,
                         cudaFuncAttributeMaxDynamicSharedMemorySize, stats_smem);
    cudaFuncSetAttribute(chunk_partial_kernel,
                         cudaFuncAttributeMaxDynamicSharedMemorySize, PART_SMEM);
    cudaFuncSetAttribute(chunk_out_kernel,
                         cudaFuncAttributeMaxDynamicSharedMemorySize, COUT_SMEM);

    qkv_mma_kernel<<<dim3(NDIM / 64, M_ROWS / 128, 3), 256, GEMM_SMEM>>>(
        x, Wq, bq, Wk, bk, Wv, bv);
    chunk_stats_kernel<<<dim3(NCHUNK, BHEADS), 256, stats_smem>>>();
    prefix_kernel<<<BHEADS, 256>>>();
    chunk_partial_kernel<<<dim3(NCHUNK, BHEADS), 256, PART_SMEM>>>();
    chunk_out_kernel<<<dim3(NCHUNK, BHEADS), 256, COUT_SMEM>>>();
    out_mma_kernel<<<dim3(NDIM / 64, M_ROWS / 128), 256, GEMM_SMEM>>>(Wo, bo, out);
}

// round 12
// speedup vs baseline: 1.7307x; 1.0382x over previous
#include <cuda_runtime.h>
#include <cuda_fp16.h>
#include <cstdint>

// Problem constants
#define S_LEN  2048
#define DIMV   1024
#define NHEAD  16
#define HD     64
#define BATCH  2
#define M_ROWS (BATCH * S_LEN)     // 4096
#define KDIM   1024
#define NDIM   1024
#define BHEADS (BATCH * NHEAD)     // 32
#define CHUNK  128
#define NCHUNK (S_LEN / CHUNK)     // 16
#define WSZ    (NDIM * KDIM)

// ---------------------------------------------------------------------------
// Scratch (static device globals)
// ---------------------------------------------------------------------------
__device__ float g_q[M_ROWS * DIMV];
__device__ float g_k[M_ROWS * DIMV];
__device__ float g_v[M_ROWS * DIMV];
__device__ float g_att[M_ROWS * DIMV];
__device__ float g_ckv[BHEADS * NCHUNK * HD * HD];
__device__ float g_ck1[BHEADS * NCHUNK * HD];
__device__ float g_pkv[BHEADS * NCHUNK * HD * HD];
__device__ float g_pk1[BHEADS * NCHUNK * HD];
__device__ float g_den[BHEADS * NCHUNK * CHUNK];
__device__ __half g_ah16[M_ROWS * KDIM];   // activation hi (x, then att)
__device__ __half g_al16[M_ROWS * KDIM];   // activation lo
__device__ __half g_wh16[4 * WSZ];         // weight hi: Wq,Wk,Wv,Wo
__device__ __half g_wl16[4 * WSZ];         // weight lo

#define SMS 132  // padded shared stride for the fp32 attention kernels

// ===========================================================================
// Helpers
// ===========================================================================
__device__ __forceinline__ uint32_t smem_u32(const void* p) {
    uint32_t a;
    asm("{ .reg .u64 t; cvta.to.shared.u64 t, %1; cvt.u32.u64 %0, t; }"
        : "=r"(a) : "l"(p));
    return a;
}

__device__ __forceinline__ uint32_t h2u(__half2 h) {
    return *reinterpret_cast<uint32_t*>(&h);
}

__device__ __forceinline__ void mma_f16(float* d, const uint32_t* a,
                                        uint32_t b0, uint32_t b1) {
    asm volatile(
        "mma.sync.aligned.m16n8k16.row.col.f32.f16.f16.f32 "
        "{%0,%1,%2,%3}, {%4,%5,%6,%7}, {%8,%9}, {%0,%1,%2,%3};"
        : "+f"(d[0]), "+f"(d[1]), "+f"(d[2]), "+f"(d[3])
        : "r"(a[0]), "r"(a[1]), "r"(a[2]), "r"(a[3]), "r"(b0), "r"(b1));
}

__device__ __forceinline__ void cvt8(float4 a, float4 b, uint4& hi, uint4& lo)
{
    __half2 h0 = __floats2half2_rn(a.x, a.y);
    __half2 h1 = __floats2half2_rn(a.z, a.w);
    __half2 h2 = __floats2half2_rn(b.x, b.y);
    __half2 h3 = __floats2half2_rn(b.z, b.w);
    float2 f0 = __half22float2(h0);
    float2 f1 = __half22float2(h1);
    float2 f2 = __half22float2(h2);
    float2 f3 = __half22float2(h3);
    __half2 l0 = __floats2half2_rn(a.x - f0.x, a.y - f0.y);
    __half2 l1 = __floats2half2_rn(a.z - f1.x, a.w - f1.y);
    __half2 l2 = __floats2half2_rn(b.x - f2.x, b.y - f2.y);
    __half2 l3 = __floats2half2_rn(b.z - f3.x, b.w - f3.y);
    hi.x = h2u(h0); hi.y = h2u(h1); hi.z = h2u(h2); hi.w = h2u(h3);
    lo.x = h2u(l0); lo.y = h2u(l1); lo.z = h2u(l2); lo.w = h2u(l3);
}

__device__ __forceinline__ void cp16(uint32_t saddr, const void* g) {
    asm volatile("cp.async.cg.shared.global [%0], [%1], 16;"
                 :: "r"(saddr), "l"(g));
}
#define CP_COMMIT() asm volatile("cp.async.commit_group;" ::: "memory")
#define CP_WAIT1()  asm volatile("cp.async.wait_group 1;" ::: "memory")
#define CP_WAIT0()  asm volatile("cp.async.wait_group 0;" ::: "memory")

// ---------------------------------------------------------------------------
// fp16 hi/lo split prep: hi = rn_f16(v), lo = rn_f16(v - hi)
// ---------------------------------------------------------------------------
__device__ __forceinline__ void split16_body(
    const float* __restrict__ src, __half* __restrict__ hi,
    __half* __restrict__ lo, int n8)
{
    int i = blockIdx.x * blockDim.x + threadIdx.x;
    const int stride = gridDim.x * blockDim.x;
    for (; i < n8; i += stride) {
        const float4 a = ((const float4*)src)[2 * i];
        const float4 b = ((const float4*)src)[2 * i + 1];
        uint4 h, l;
        cvt8(a, b, h, l);
        ((uint4*)hi)[i] = h;
        ((uint4*)lo)[i] = l;
    }
}

__global__ void __launch_bounds__(256) split_act16_kernel(const float* __restrict__ src)
{
    split16_body(src, g_ah16, g_al16, M_ROWS * KDIM / 8);
}
__global__ void __launch_bounds__(256) split_att16_kernel()
{
    split16_body(g_att, g_ah16, g_al16, M_ROWS * KDIM / 8);
}
__global__ void __launch_bounds__(256) split_w16_kernel(const float* __restrict__ src, int slot)
{
    split16_body(src, g_wh16 + (size_t)slot * WSZ, g_wl16 + (size_t)slot * WSZ, WSZ / 8);
}

// ===========================================================================
// Pre-split fp16 GEMM (3-pass), cp.async 3-stage ring, BK=32.
// CTA 128(M)x64(N), 256 threads, 8 warps 4x2, 32x32 warp tiles.
// Smem row stride 20 words (16 data + 4 pad): fragment LDS conflict-free.
// ===========================================================================
#define BK32  32
#define NKS32 (KDIM / BK32)   // 32
#define RW    20              // words per smem row
#define TA    (128 * RW)      // 2560 words per A tile (hi or lo)
#define TB    (64 * RW)       // 1280 words per B tile
#define OAH   0
#define OAL   TA
#define OBH   (2 * TA)
#define OBL   (2 * TA + TB)
#define STW   (2 * TA + 2 * TB)      // 7680 words per stage
#define GSM   (3 * STW * 4)          // 92160 bytes

__device__ __forceinline__ void gemm_pre16(
    const __half* __restrict__ Ah, const __half* __restrict__ Al,
    const __half* __restrict__ Bh, const __half* __restrict__ Bl,
    const float* __restrict__ bias, float* __restrict__ out, int doExp,
    int m0, int n0)
{
    extern __shared__ uint32_t su[];
    const uint32_t shb = smem_u32(su);

    const int tid = threadIdx.x;
    const int lane = tid & 31, wid = tid >> 5;
    const int wm = wid >> 1, wn = wid & 1;       // 4 x 2 warp grid
    const int grp = lane >> 2, tig = lane & 3;

    // A load coords: 2 thr/row, each 32B (2 cp16)
    const int rA = tid >> 1, hA = tid & 1;
    const __half* pAh = Ah + (size_t)(m0 + rA) * KDIM + hA * 16;
    const __half* pAl = Al + (size_t)(m0 + rA) * KDIM + hA * 16;
    const uint32_t sA = (uint32_t)(rA * RW + hA * 8) * 4u;
    // B load coords: 4 thr/row, each 16B (1 cp16)
    const int rB = tid >> 2, qB = tid & 3;
    const __half* pBh = Bh + (size_t)(n0 + rB) * KDIM + qB * 8;
    const __half* pBl = Bl + (size_t)(n0 + rB) * KDIM + qB * 8;
    const uint32_t sB = (uint32_t)(rB * RW + qB * 4) * 4u;

    float acc[2][4][4];
#pragma unroll
    for (int mt = 0; mt < 2; mt++)
#pragma unroll
        for (int nt = 0; nt < 4; nt++)
#pragma unroll
            for (int e = 0; e < 4; e++) acc[mt][nt][e] = 0.f;

#define ISSUE(s_) do {                                                   \
    const int s__ = (s_);                                                \
    const int k0__ = s__ * BK32;                                         \
    const uint32_t sb__ = shb + (uint32_t)((s__ % 3) * STW) * 4u;        \
    cp16(sb__ + OAH * 4 + sA,      pAh + k0__);                          \
    cp16(sb__ + OAH * 4 + sA + 16, pAh + k0__ + 8);                      \
    cp16(sb__ + OAL * 4 + sA,      pAl + k0__);                          \
    cp16(sb__ + OAL * 4 + sA + 16, pAl + k0__ + 8);                      \
    cp16(sb__ + OBH * 4 + sB,      pBh + k0__);                          \
    cp16(sb__ + OBL * 4 + sB,      pBl + k0__);                          \
    CP_COMMIT();                                                         \
} while (0)

    ISSUE(0);
    ISSUE(1);

    for (int s = 0; s < NKS32; s++) {
        if (s + 1 < NKS32) CP_WAIT1(); else CP_WAIT0();
        __syncthreads();
        if (s + 2 < NKS32) ISSUE(s + 2);

        const uint32_t* bu = su + (s % 3) * STW;
#pragma unroll
        for (int k16 = 0; k16 < 2; k16++) {
            const int wb = k16 * 8;
            uint32_t ah[2][4], al[2][4];
#pragma unroll
            for (int mt = 0; mt < 2; mt++) {
                const int ro = (wm * 32 + mt * 16 + grp) * RW;
                ah[mt][0] = bu[OAH + ro + wb + tig];
                ah[mt][1] = bu[OAH + ro + 8 * RW + wb + tig];
                ah[mt][2] = bu[OAH + ro + wb + tig + 4];
                ah[mt][3] = bu[OAH + ro + 8 * RW + wb + tig + 4];
                al[mt][0] = bu[OAL + ro + wb + tig];
                al[mt][1] = bu[OAL + ro + 8 * RW + wb + tig];
                al[mt][2] = bu[OAL + ro + wb + tig + 4];
                al[mt][3] = bu[OAL + ro + 8 * RW + wb + tig + 4];
            }
#pragma unroll
            for (int nt = 0; nt < 4; nt++) {
                const int ro = (wn * 32 + nt * 8 + grp) * RW;
                const uint32_t bh0 = bu[OBH + ro + wb + tig];
                const uint32_t bh1 = bu[OBH + ro + wb + tig + 4];
                const uint32_t bl0 = bu[OBL + ro + wb + tig];
                const uint32_t bl1 = bu[OBL + ro + wb + tig + 4];
#pragma unroll
                for (int mt = 0; mt < 2; mt++) {
                    mma_f16(acc[mt][nt], ah[mt], bh0, bh1);
                    mma_f16(acc[mt][nt], ah[mt], bl0, bl1);
                    mma_f16(acc[mt][nt], al[mt], bh0, bh1);
                }
            }
        }
        __syncthreads();
    }
#undef ISSUE

    // epilogue
#pragma unroll
    for (int mt = 0; mt < 2; mt++) {
        const int rr = m0 + wm * 32 + mt * 16 + grp;
#pragma unroll
        for (int nt = 0; nt < 4; nt++) {
            const int cc = n0 + wn * 32 + nt * 8 + 2 * tig;
            const float bb0 = bias[cc], bb1 = bias[cc + 1];
            float v0 = acc[mt][nt][0] + bb0;
            float v1 = acc[mt][nt][1] + bb1;
            float v2 = acc[mt][nt][2] + bb0;
            float v3 = acc[mt][nt][3] + bb1;
            if (doExp) {
                v0 = expf(v0); v1 = expf(v1); v2 = expf(v2); v3 = expf(v3);
            }
            float2 p0; p0.x = v0; p0.y = v1;
            float2 p1; p1.x = v2; p1.y = v3;
            *(float2*)&out[(size_t)rr * NDIM + cc]       = p0;
            *(float2*)&out[(size_t)(rr + 8) * NDIM + cc] = p1;
        }
    }
}

__global__ void __launch_bounds__(256, 2) qkv_mma_kernel(
    const float* __restrict__ bq, const float* __restrict__ bk,
    const float* __restrict__ bv)
{
    const int z = blockIdx.z;
    const float* bias = (z == 0) ? bq : ((z == 1) ? bk : bv);
    float* out        = (z == 0) ? g_q : ((z == 1) ? g_k : g_v);
    gemm_pre16(g_ah16, g_al16,
               g_wh16 + (size_t)z * WSZ, g_wl16 + (size_t)z * WSZ,
               bias, out, z < 2, blockIdx.y * 128, blockIdx.x * 64);
}

__global__ void __launch_bounds__(256, 2) out_mma_kernel(
    const float* __restrict__ bo, float* __restrict__ out)
{
    gemm_pre16(g_ah16, g_al16,
               g_wh16 + (size_t)3 * WSZ, g_wl16 + (size_t)3 * WSZ,
               bo, out, 0, blockIdx.y * 128, blockIdx.x * 64);
}

// ---------------------------------------------------------------------------
// Chunk stats: per (head, chunk) compute sum_t k_t v_t^T (64x64) and sum_t k_t
// ---------------------------------------------------------------------------
__global__ void __launch_bounds__(256) chunk_stats_kernel()
{
    extern __shared__ __align__(16) float sm[];
    float* Ks = sm;
    float* Vs = sm + CHUNK * HD;
    const int bh = blockIdx.y, c = blockIdx.x;
    const int b = bh >> 4, hh = bh & 15;
    const int tid = threadIdx.x;
    const size_t base = ((size_t)(b * S_LEN + c * CHUNK)) * DIMV + hh * HD;

#pragma unroll
    for (int it = 0; it < 8; it++) {
        const int idx = tid + it * 256;
        const int t = idx >> 4, dv = idx & 15;
        *(float4*)&Ks[t * HD + dv * 4] =
            *(const float4*)(g_k + base + (size_t)t * DIMV + dv * 4);
        *(float4*)&Vs[t * HD + dv * 4] =
            *(const float4*)(g_v + base + (size_t)t * DIMV + dv * 4);
    }
    __syncthreads();

    const int tx = tid & 15, ty = tid >> 4;
    float acc[4][4];
#pragma unroll
    for (int i = 0; i < 4; i++)
#pragma unroll
        for (int j = 0; j < 4; j++) acc[i][j] = 0.f;

#pragma unroll 4
    for (int t = 0; t < CHUNK; t++) {
        float kf[4], vf[4];
        *(float4*)kf = *(const float4*)&Ks[t * HD + ty * 4];
        *(float4*)vf = *(const float4*)&Vs[t * HD + tx * 4];
#pragma unroll
        for (int i = 0; i < 4; i++)
#pragma unroll
            for (int j = 0; j < 4; j++)
                acc[i][j] = fmaf(kf[i], vf[j], acc[i][j]);
    }

    float* okv = g_ckv + ((size_t)bh * NCHUNK + c) * HD * HD;
#pragma unroll
    for (int i = 0; i < 4; i++)
        *(float4*)&okv[(ty * 4 + i) * HD + tx * 4] = *(float4*)acc[i];

    if (tid < HD) {
        float s = 0.f;
#pragma unroll 8
        for (int t = 0; t < CHUNK; t++) s += Ks[t * HD + tid];
        g_ck1[((size_t)bh * NCHUNK + c) * HD + tid] = s;
    }
}

// ---------------------------------------------------------------------------
// Exclusive prefix over the 16 chunk states per head
// ---------------------------------------------------------------------------
__global__ void __launch_bounds__(256) prefix_kernel()
{
    const int bh = blockIdx.x, tid = threadIdx.x;
    for (int e = tid; e < HD * HD; e += 256) {
        float run = 0.f;
#pragma unroll
        for (int c = 0; c < NCHUNK; c++) {
            const size_t off = ((size_t)bh * NCHUNK + c) * HD * HD + e;
            g_pkv[off] = run;
            run += g_ckv[off];
        }
    }
    if (tid < HD) {
        float run = 0.f;
#pragma unroll
        for (int c = 0; c < NCHUNK; c++) {
            const size_t off = ((size_t)bh * NCHUNK + c) * HD + tid;
            g_pk1[off] = run;
            run += g_ck1[off];
        }
    }
}

// ---------------------------------------------------------------------------
// Chunk partial (inter-chunk): g_att = Q @ Sp (partial), g_den = q . k1prefix
// ---------------------------------------------------------------------------
#define QS   68
#define PART_SMEM ((CHUNK * QS + HD * QS + HD) * 4)

__global__ void __launch_bounds__(256) chunk_partial_kernel()
{
    extern __shared__ __align__(16) float sm[];
    float* Qs  = sm;
    float* Sps = sm + CHUNK * QS;
    float* k1s = Sps + HD * QS;

    const int bh = blockIdx.y, c = blockIdx.x;
    const int b = bh >> 4, hh = bh & 15;
    const int tid = threadIdx.x;
    const size_t base = ((size_t)(b * S_LEN + c * CHUNK)) * DIMV + hh * HD;
    const float* spg = g_pkv + ((size_t)bh * NCHUNK + c) * HD * HD;

#pragma unroll
    for (int it = 0; it < 8; it++) {
        const int idx = tid + it * 256;
        const int t = idx >> 4, dv = idx & 15;
        *(float4*)&Qs[t * QS + dv * 4] =
            *(const float4*)(g_q + base + (size_t)t * DIMV + dv * 4);
    }
#pragma unroll
    for (int it = 0; it < 4; it++) {
        const int idx = tid + it * 256;
        const int d1 = idx >> 4, dv = idx & 15;
        *(float4*)&Sps[d1 * QS + dv * 4] = *(const float4*)(spg + d1 * HD + dv * 4);
    }
    if (tid < HD) k1s[tid] = g_pk1[((size_t)bh * NCHUNK + c) * HD + tid];
    __syncthreads();

    const int tx = tid & 15, ty = tid >> 4;
    float acc[8][4];
#pragma unroll
    for (int i = 0; i < 8; i++)
#pragma unroll
        for (int j = 0; j < 4; j++) acc[i][j] = 0.f;

#pragma unroll 4
    for (int d1 = 0; d1 < HD; d1++) {
        float vf[4];
        *(float4*)vf = *(const float4*)&Sps[d1 * QS + tx * 4];
#pragma unroll
        for (int i = 0; i < 8; i++) {
            const float a = Qs[(ty * 8 + i) * QS + d1];
#pragma unroll
            for (int j = 0; j < 4; j++) acc[i][j] = fmaf(a, vf[j], acc[i][j]);
        }
    }

#pragma unroll
    for (int i = 0; i < 8; i++) {
        const int t = ty * 8 + i;
        *(float4*)(g_att + base + (size_t)t * DIMV + tx * 4) = *(float4*)acc[i];
    }

    if (tid < CHUNK) {
        float s = 0.f;
#pragma unroll 8
        for (int d = 0; d < HD; d++) s = fmaf(Qs[tid * QS + d], k1s[d], s);
        g_den[((size_t)bh * NCHUNK + c) * CHUNK + tid] = s;
    }
}

// ---------------------------------------------------------------------------
// Chunk output (intra-chunk): A = QK^T masked; out = (partial + A@V)/den.
// Am overlays QsT+KsT after phase 2. smem 98KB -> 2 CTAs/SM.
// ---------------------------------------------------------------------------
#define COUT_SMEM ((2 * HD * SMS + CHUNK * HD) * 4)

__global__ void __launch_bounds__(256, 2) chunk_out_kernel()
{
    extern __shared__ __align__(16) float sm[];
    float* QsT = sm;
    float* KsT = sm + HD * SMS;
    float* Am  = sm;
    float* Vs  = sm + 2 * HD * SMS;
    __shared__ float dens[CHUNK];

    const int bh = blockIdx.y, c = blockIdx.x;
    const int b = bh >> 4, hh = bh & 15;
    const int tid = threadIdx.x;
    const size_t base = ((size_t)(b * S_LEN + c * CHUNK)) * DIMV + hh * HD;

#pragma unroll
    for (int it = 0; it < 8; it++) {
        const int idx = tid + it * 256;
        const int t = idx >> 4, dv = idx & 15;
        float4 q4 = *(const float4*)(g_q + base + (size_t)t * DIMV + dv * 4);
        float4 k4 = *(const float4*)(g_k + base + (size_t)t * DIMV + dv * 4);
        float4 v4 = *(const float4*)(g_v + base + (size_t)t * DIMV + dv * 4);
        QsT[(dv * 4 + 0) * SMS + t] = q4.x;
        QsT[(dv * 4 + 1) * SMS + t] = q4.y;
        QsT[(dv * 4 + 2) * SMS + t] = q4.z;
        QsT[(dv * 4 + 3) * SMS + t] = q4.w;
        KsT[(dv * 4 + 0) * SMS + t] = k4.x;
        KsT[(dv * 4 + 1) * SMS + t] = k4.y;
        KsT[(dv * 4 + 2) * SMS + t] = k4.z;
        KsT[(dv * 4 + 3) * SMS + t] = k4.w;
        *(float4*)&Vs[t * HD + dv * 4] = v4;
    }
    __syncthreads();

    const int tx = tid & 15, ty = tid >> 4;

    float acc[8][8];
#pragma unroll
    for (int i = 0; i < 8; i++)
#pragma unroll
        for (int j = 0; j < 8; j++) acc[i][j] = 0.f;
#pragma unroll 4
    for (int kk = 0; kk < HD; kk++) {
        float qf[8], kf[8];
        *(float4*)(qf)     = *(const float4*)&QsT[kk * SMS + ty * 8];
        *(float4*)(qf + 4) = *(const float4*)&QsT[kk * SMS + ty * 8 + 4];
        *(float4*)(kf)     = *(const float4*)&KsT[kk * SMS + tx * 8];
        *(float4*)(kf + 4) = *(const float4*)&KsT[kk * SMS + tx * 8 + 4];
#pragma unroll
        for (int i = 0; i < 8; i++)
#pragma unroll
            for (int j = 0; j < 8; j++)
                acc[i][j] = fmaf(qf[i], kf[j], acc[i][j]);
    }
    __syncthreads();

#pragma unroll
    for (int i = 0; i < 8; i++) {
        const int t = ty * 8 + i;
        float o[8];
#pragma unroll
        for (int j = 0; j < 8; j++) {
            const int tp = tx * 8 + j;
            o[j] = (tp <= t) ? acc[i][j] : 0.f;
        }
        *(float4*)&Am[t * SMS + tx * 8]     = *(float4*)o;
        *(float4*)&Am[t * SMS + tx * 8 + 4] = *(float4*)(o + 4);
    }
    __syncthreads();

    if (tid < CHUNK) {
        float s = g_den[((size_t)bh * NCHUNK + c) * CHUNK + tid];
#pragma unroll 8
        for (int tp0 = 0; tp0 < CHUNK; tp0++) {
            const int tp = (tp0 + tid) & (CHUNK - 1);
            s += Am[tid * SMS + tp];
        }
        dens[tid] = 1.0f / s;
    }
    __syncthreads();

    float acc2[8][4];
#pragma unroll
    for (int i = 0; i < 8; i++)
#pragma unroll
        for (int j = 0; j < 4; j++) acc2[i][j] = 0.f;
#pragma unroll 4
    for (int tp = 0; tp < CHUNK; tp++) {
        float vf[4];
        *(float4*)vf = *(const float4*)&Vs[tp * HD + tx * 4];
#pragma unroll
        for (int i = 0; i < 8; i++) {
            const float a = Am[(ty * 8 + i) * SMS + tp];
#pragma unroll
            for (int j = 0; j < 4; j++) acc2[i][j] = fmaf(a, vf[j], acc2[i][j]);
        }
    }
#pragma unroll
    for (int i = 0; i < 8; i++) {
        const int t = ty * 8 + i;
        const float inv = dens[t];
        float4 p = *(const float4*)(g_att + base + (size_t)t * DIMV + tx * 4);
        float4 o;
        o.x = (acc2[i][0] + p.x) * inv;
        o.y = (acc2[i][1] + p.y) * inv;
        o.z = (acc2[i][2] + p.z) * inv;
        o.w = (acc2[i][3] + p.w) * inv;
        *(float4*)(g_att + base + (size_t)t * DIMV + tx * 4) = o;
    }
}

// ---------------------------------------------------------------------------
// Launch
// ---------------------------------------------------------------------------
extern "C" void kernel_launch(void* const* d_in, const int* in_sizes, int n_in,
                              void* d_out, int out_size)
{
    const float* x  = (const float*)d_in[0];
    const float* Wq = (const float*)d_in[1];
    const float* bq = (const float*)d_in[2];
    const float* Wk = (const float*)d_in[3];
    const float* bk = (const float*)d_in[4];
    const float* Wv = (const float*)d_in[5];
    const float* bv = (const float*)d_in[6];
    const float* Wo = (const float*)d_in[7];
    const float* bo = (const float*)d_in[8];
    float* out = (float*)d_out;

    const int stats_smem = 2 * CHUNK * HD * (int)sizeof(float);
    cudaFuncSetAttribute(qkv_mma_kernel,
                         cudaFuncAttributeMaxDynamicSharedMemorySize, GSM);
    cudaFuncSetAttribute(out_mma_kernel,
                         cudaFuncAttributeMaxDynamicSharedMemorySize, GSM);
    cudaFuncSetAttribute(chunk_stats_kernel,
                         cudaFuncAttributeMaxDynamicSharedMemorySize, stats_smem);
    cudaFuncSetAttribute(chunk_partial_kernel,
                         cudaFuncAttributeMaxDynamicSharedMemorySize, PART_SMEM);
    cudaFuncSetAttribute(chunk_out_kernel,
                         cudaFuncAttributeMaxDynamicSharedMemorySize, COUT_SMEM);

    // 1. fp16 hi/lo prep (byte-neutral vs fp32)
    split_act16_kernel<<<512, 256>>>(x);
    split_w16_kernel<<<256, 256>>>(Wq, 0);
    split_w16_kernel<<<256, 256>>>(Wk, 1);
    split_w16_kernel<<<256, 256>>>(Wv, 2);
    split_w16_kernel<<<256, 256>>>(Wo, 3);

    // 2. QKV projections (+exp for q,k)
    qkv_mma_kernel<<<dim3(NDIM / 64, M_ROWS / 128, 3), 256, GSM>>>(bq, bk, bv);

    // 3. chunked linear attention
    chunk_stats_kernel<<<dim3(NCHUNK, BHEADS), 256, stats_smem>>>();
    prefix_kernel<<<BHEADS, 256>>>();
    chunk_partial_kernel<<<dim3(NCHUNK, BHEADS), 256, PART_SMEM>>>();
    chunk_out_kernel<<<dim3(NCHUNK, BHEADS), 256, COUT_SMEM>>>();

    // 4. output projection
    split_att16_kernel<<<512, 256>>>();
    out_mma_kernel<<<dim3(NDIM / 64, M_ROWS / 128), 256, GSM>>>(bo, out);
}

// round 14
// speedup vs baseline: 1.9217x; 1.1104x over previous
#include <cuda_runtime.h>
#include <cuda_fp16.h>
#include <cstdint>

// Problem constants
#define S_LEN  2048
#define DIMV   1024
#define NHEAD  16
#define HD     64
#define BATCH  2
#define M_ROWS (BATCH * S_LEN)     // 4096
#define KDIM   1024
#define NDIM   1024
#define BHEADS (BATCH * NHEAD)     // 32
#define CHUNK  128
#define NCHUNK (S_LEN / CHUNK)     // 16
#define WSZ    (NDIM * KDIM)

// ---------------------------------------------------------------------------
// Scratch (static device globals)
// ---------------------------------------------------------------------------
__device__ float g_q[M_ROWS * DIMV];
__device__ float g_k[M_ROWS * DIMV];
__device__ float g_v[M_ROWS * DIMV];
__device__ float g_att[M_ROWS * DIMV];
__device__ float g_ckv[BHEADS * NCHUNK * HD * HD];
__device__ float g_ck1[BHEADS * NCHUNK * HD];
__device__ float g_pkv[BHEADS * NCHUNK * HD * HD];
__device__ float g_pk1[BHEADS * NCHUNK * HD];
__device__ float g_den[BHEADS * NCHUNK * CHUNK];
__device__ __half g_ah16[M_ROWS * KDIM];   // activation hi (x, then att)
__device__ __half g_al16[M_ROWS * KDIM];   // activation lo
__device__ __half g_wh16[4 * WSZ];         // weight hi: Wq,Wk,Wv,Wo
__device__ __half g_wl16[4 * WSZ];         // weight lo

#define SMS 132  // padded shared stride for the fp32 attention kernels

// ===========================================================================
// Helpers
// ===========================================================================
__device__ __forceinline__ uint32_t smem_u32(const void* p) {
    uint32_t a;
    asm("{ .reg .u64 t; cvta.to.shared.u64 t, %1; cvt.u32.u64 %0, t; }"
        : "=r"(a) : "l"(p));
    return a;
}

__device__ __forceinline__ uint32_t h2u(__half2 h) {
    return *reinterpret_cast<uint32_t*>(&h);
}

__device__ __forceinline__ void mma_f16(float* d, const uint32_t* a,
                                        uint32_t b0, uint32_t b1) {
    asm volatile(
        "mma.sync.aligned.m16n8k16.row.col.f32.f16.f16.f32 "
        "{%0,%1,%2,%3}, {%4,%5,%6,%7}, {%8,%9}, {%0,%1,%2,%3};"
        : "+f"(d[0]), "+f"(d[1]), "+f"(d[2]), "+f"(d[3])
        : "r"(a[0]), "r"(a[1]), "r"(a[2]), "r"(a[3]), "r"(b0), "r"(b1));
}

__device__ __forceinline__ void cvt8(float4 a, float4 b, uint4& hi, uint4& lo)
{
    __half2 h0 = __floats2half2_rn(a.x, a.y);
    __half2 h1 = __floats2half2_rn(a.z, a.w);
    __half2 h2 = __floats2half2_rn(b.x, b.y);
    __half2 h3 = __floats2half2_rn(b.z, b.w);
    float2 f0 = __half22float2(h0);
    float2 f1 = __half22float2(h1);
    float2 f2 = __half22float2(h2);
    float2 f3 = __half22float2(h3);
    __half2 l0 = __floats2half2_rn(a.x - f0.x, a.y - f0.y);
    __half2 l1 = __floats2half2_rn(a.z - f1.x, a.w - f1.y);
    __half2 l2 = __floats2half2_rn(b.x - f2.x, b.y - f2.y);
    __half2 l3 = __floats2half2_rn(b.z - f3.x, b.w - f3.y);
    hi.x = h2u(h0); hi.y = h2u(h1); hi.z = h2u(h2); hi.w = h2u(h3);
    lo.x = h2u(l0); lo.y = h2u(l1); lo.z = h2u(l2); lo.w = h2u(l3);
}

__device__ __forceinline__ void cp16(uint32_t saddr, const void* g) {
    asm volatile("cp.async.cg.shared.global [%0], [%1], 16;"
                 :: "r"(saddr), "l"(g));
}
#define CP_COMMIT() asm volatile("cp.async.commit_group;" ::: "memory")
#define CP_WAIT1()  asm volatile("cp.async.wait_group 1;" ::: "memory")
#define CP_WAIT0()  asm volatile("cp.async.wait_group 0;" ::: "memory")

// ---------------------------------------------------------------------------
// fp16 hi/lo split prep: hi = rn_f16(v), lo = rn_f16(v - hi)
// ---------------------------------------------------------------------------
__device__ __forceinline__ void split16_body(
    const float* __restrict__ src, __half* __restrict__ hi,
    __half* __restrict__ lo, int n8)
{
    int i = blockIdx.x * blockDim.x + threadIdx.x;
    const int stride = gridDim.x * blockDim.x;
    for (; i < n8; i += stride) {
        const float4 a = ((const float4*)src)[2 * i];
        const float4 b = ((const float4*)src)[2 * i + 1];
        uint4 h, l;
        cvt8(a, b, h, l);
        ((uint4*)hi)[i] = h;
        ((uint4*)lo)[i] = l;
    }
}

__global__ void __launch_bounds__(256) split_act16_kernel(const float* __restrict__ src)
{
    split16_body(src, g_ah16, g_al16, M_ROWS * KDIM / 8);
}
__global__ void __launch_bounds__(256) split_att16_kernel()
{
    split16_body(g_att, g_ah16, g_al16, M_ROWS * KDIM / 8);
}
__global__ void __launch_bounds__(256) split_w16_kernel(const float* __restrict__ src, int slot)
{
    split16_body(src, g_wh16 + (size_t)slot * WSZ, g_wl16 + (size_t)slot * WSZ, WSZ / 8);
}

// ===========================================================================
// Pre-split fp16 GEMM, cp.async 3-stage ring, BK=32.
// PASSES=3: ah*bh + ah*bl + al*bh (22-bit). PASSES=2: ah*bh + ah*bl
// (A-lo dropped: ~2^-12 rel err; A-lo cp.asyncs skipped entirely).
// CTA 128(M)x64(N), 256 threads, 8 warps 4x2, 32x32 warp tiles.
// ===========================================================================
#define BK32  32
#define NKS32 (KDIM / BK32)   // 32
#define RW    20              // words per smem row (16 data + 4 pad)
#define TA    (128 * RW)      // 2560 words per A tile (hi or lo)
#define TB    (64 * RW)       // 1280 words per B tile
#define OAH   0
#define OAL   TA
#define OBH   (2 * TA)
#define OBL   (2 * TA + TB)
#define STW   (2 * TA + 2 * TB)      // 7680 words per stage
#define GSM   (3 * STW * 4)          // 92160 bytes

template<int PASSES, bool DOEXP>
__device__ __forceinline__ void gemm_pre16(
    const __half* __restrict__ Ah, const __half* __restrict__ Al,
    const __half* __restrict__ Bh, const __half* __restrict__ Bl,
    const float* __restrict__ bias, float* __restrict__ out,
    int m0, int n0)
{
    extern __shared__ uint32_t su[];
    const uint32_t shb = smem_u32(su);

    const int tid = threadIdx.x;
    const int lane = tid & 31, wid = tid >> 5;
    const int wm = wid >> 1, wn = wid & 1;       // 4 x 2 warp grid
    const int grp = lane >> 2, tig = lane & 3;

    const int rA = tid >> 1, hA = tid & 1;
    const __half* pAh = Ah + (size_t)(m0 + rA) * KDIM + hA * 16;
    const __half* pAl = Al + (size_t)(m0 + rA) * KDIM + hA * 16;
    const uint32_t sA = (uint32_t)(rA * RW + hA * 8) * 4u;
    const int rB = tid >> 2, qB = tid & 3;
    const __half* pBh = Bh + (size_t)(n0 + rB) * KDIM + qB * 8;
    const __half* pBl = Bl + (size_t)(n0 + rB) * KDIM + qB * 8;
    const uint32_t sB = (uint32_t)(rB * RW + qB * 4) * 4u;

    float acc[2][4][4];
#pragma unroll
    for (int mt = 0; mt < 2; mt++)
#pragma unroll
        for (int nt = 0; nt < 4; nt++)
#pragma unroll
            for (int e = 0; e < 4; e++) acc[mt][nt][e] = 0.f;

#define ISSUE(s_) do {                                                   \
    const int s__ = (s_);                                                \
    const int k0__ = s__ * BK32;                                         \
    const uint32_t sb__ = shb + (uint32_t)((s__ % 3) * STW) * 4u;        \
    cp16(sb__ + OAH * 4 + sA,      pAh + k0__);                          \
    cp16(sb__ + OAH * 4 + sA + 16, pAh + k0__ + 8);                      \
    if (PASSES == 3) {                                                   \
        cp16(sb__ + OAL * 4 + sA,      pAl + k0__);                      \
        cp16(sb__ + OAL * 4 + sA + 16, pAl + k0__ + 8);                  \
    }                                                                    \
    cp16(sb__ + OBH * 4 + sB,      pBh + k0__);                          \
    cp16(sb__ + OBL * 4 + sB,      pBl + k0__);                          \
    CP_COMMIT();                                                         \
} while (0)

    ISSUE(0);
    ISSUE(1);

    for (int s = 0; s < NKS32; s++) {
        if (s + 1 < NKS32) CP_WAIT1(); else CP_WAIT0();
        __syncthreads();
        if (s + 2 < NKS32) ISSUE(s + 2);

        const uint32_t* bu = su + (s % 3) * STW;
#pragma unroll
        for (int k16 = 0; k16 < 2; k16++) {
            const int wb = k16 * 8;
            uint32_t ah[2][4], al[2][4];
#pragma unroll
            for (int mt = 0; mt < 2; mt++) {
                const int ro = (wm * 32 + mt * 16 + grp) * RW;
                ah[mt][0] = bu[OAH + ro + wb + tig];
                ah[mt][1] = bu[OAH + ro + 8 * RW + wb + tig];
                ah[mt][2] = bu[OAH + ro + wb + tig + 4];
                ah[mt][3] = bu[OAH + ro + 8 * RW + wb + tig + 4];
                if (PASSES == 3) {
                    al[mt][0] = bu[OAL + ro + wb + tig];
                    al[mt][1] = bu[OAL + ro + 8 * RW + wb + tig];
                    al[mt][2] = bu[OAL + ro + wb + tig + 4];
                    al[mt][3] = bu[OAL + ro + 8 * RW + wb + tig + 4];
                }
            }
#pragma unroll
            for (int nt = 0; nt < 4; nt++) {
                const int ro = (wn * 32 + nt * 8 + grp) * RW;
                const uint32_t bh0 = bu[OBH + ro + wb + tig];
                const uint32_t bh1 = bu[OBH + ro + wb + tig + 4];
                const uint32_t bl0 = bu[OBL + ro + wb + tig];
                const uint32_t bl1 = bu[OBL + ro + wb + tig + 4];
#pragma unroll
                for (int mt = 0; mt < 2; mt++) {
                    mma_f16(acc[mt][nt], ah[mt], bh0, bh1);
                    mma_f16(acc[mt][nt], ah[mt], bl0, bl1);
                    if (PASSES == 3) mma_f16(acc[mt][nt], al[mt], bh0, bh1);
                }
            }
        }
        __syncthreads();
    }
#undef ISSUE

    // epilogue
#pragma unroll
    for (int mt = 0; mt < 2; mt++) {
        const int rr = m0 + wm * 32 + mt * 16 + grp;
#pragma unroll
        for (int nt = 0; nt < 4; nt++) {
            const int cc = n0 + wn * 32 + nt * 8 + 2 * tig;
            const float bb0 = bias[cc], bb1 = bias[cc + 1];
            float v0 = acc[mt][nt][0] + bb0;
            float v1 = acc[mt][nt][1] + bb1;
            float v2 = acc[mt][nt][2] + bb0;
            float v3 = acc[mt][nt][3] + bb1;
            if (DOEXP) {
                v0 = expf(v0); v1 = expf(v1); v2 = expf(v2); v3 = expf(v3);
            }
            float2 p0; p0.x = v0; p0.y = v1;
            float2 p1; p1.x = v2; p1.y = v3;
            *(float2*)&out[(size_t)rr * NDIM + cc]       = p0;
            *(float2*)&out[(size_t)(rr + 8) * NDIM + cc] = p1;
        }
    }
}

// Q,K: 3-pass (exp amplifies abs error) + exp epilogue
__global__ void __launch_bounds__(256, 2) qk_mma_kernel(
    const float* __restrict__ bq, const float* __restrict__ bk)
{
    const int z = blockIdx.z;                 // 0 = Q, 1 = K
    const float* bias = (z == 0) ? bq : bk;
    float* out        = (z == 0) ? g_q : g_k;
    gemm_pre16<3, true>(g_ah16, g_al16,
                        g_wh16 + (size_t)z * WSZ, g_wl16 + (size_t)z * WSZ,
                        bias, out, blockIdx.y * 128, blockIdx.x * 64);
}

// V: 2-pass (error stays relative)
__global__ void __launch_bounds__(256, 2) v_mma_kernel(const float* __restrict__ bv)
{
    gemm_pre16<2, false>(g_ah16, g_al16,
                         g_wh16 + (size_t)2 * WSZ, g_wl16 + (size_t)2 * WSZ,
                         bv, g_v, blockIdx.y * 128, blockIdx.x * 64);
}

// Out-proj: 2-pass
__global__ void __launch_bounds__(256, 2) out_mma_kernel(
    const float* __restrict__ bo, float* __restrict__ out)
{
    gemm_pre16<2, false>(g_ah16, g_al16,
                         g_wh16 + (size_t)3 * WSZ, g_wl16 + (size_t)3 * WSZ,
                         bo, out, blockIdx.y * 128, blockIdx.x * 64);
}

// ---------------------------------------------------------------------------
// Chunk stats: per (head, chunk) compute sum_t k_t v_t^T (64x64) and sum_t k_t
// ---------------------------------------------------------------------------
__global__ void __launch_bounds__(256) chunk_stats_kernel()
{
    extern __shared__ __align__(16) float sm[];
    float* Ks = sm;
    float* Vs = sm + CHUNK * HD;
    const int bh = blockIdx.y, c = blockIdx.x;
    const int b = bh >> 4, hh = bh & 15;
    const int tid = threadIdx.x;
    const size_t base = ((size_t)(b * S_LEN + c * CHUNK)) * DIMV + hh * HD;

#pragma unroll
    for (int it = 0; it < 8; it++) {
        const int idx = tid + it * 256;
        const int t = idx >> 4, dv = idx & 15;
        *(float4*)&Ks[t * HD + dv * 4] =
            *(const float4*)(g_k + base + (size_t)t * DIMV + dv * 4);
        *(float4*)&Vs[t * HD + dv * 4] =
            *(const float4*)(g_v + base + (size_t)t * DIMV + dv * 4);
    }
    __syncthreads();

    const int tx = tid & 15, ty = tid >> 4;
    float acc[4][4];
#pragma unroll
    for (int i = 0; i < 4; i++)
#pragma unroll
        for (int j = 0; j < 4; j++) acc[i][j] = 0.f;

#pragma unroll 4
    for (int t = 0; t < CHUNK; t++) {
        float kf[4], vf[4];
        *(float4*)kf = *(const float4*)&Ks[t * HD + ty * 4];
        *(float4*)vf = *(const float4*)&Vs[t * HD + tx * 4];
#pragma unroll
        for (int i = 0; i < 4; i++)
#pragma unroll
            for (int j = 0; j < 4; j++)
                acc[i][j] = fmaf(kf[i], vf[j], acc[i][j]);
    }

    float* okv = g_ckv + ((size_t)bh * NCHUNK + c) * HD * HD;
#pragma unroll
    for (int i = 0; i < 4; i++)
        *(float4*)&okv[(ty * 4 + i) * HD + tx * 4] = *(float4*)acc[i];

    if (tid < HD) {
        float s = 0.f;
#pragma unroll 8
        for (int t = 0; t < CHUNK; t++) s += Ks[t * HD + tid];
        g_ck1[((size_t)bh * NCHUNK + c) * HD + tid] = s;
    }
}

// ---------------------------------------------------------------------------
// Exclusive prefix over the 16 chunk states per head
// ---------------------------------------------------------------------------
__global__ void __launch_bounds__(256) prefix_kernel()
{
    const int bh = blockIdx.x, tid = threadIdx.x;
    for (int e = tid; e < HD * HD; e += 256) {
        float run = 0.f;
#pragma unroll
        for (int c = 0; c < NCHUNK; c++) {
            const size_t off = ((size_t)bh * NCHUNK + c) * HD * HD + e;
            g_pkv[off] = run;
            run += g_ckv[off];
        }
    }
    if (tid < HD) {
        float run = 0.f;
#pragma unroll
        for (int c = 0; c < NCHUNK; c++) {
            const size_t off = ((size_t)bh * NCHUNK + c) * HD + tid;
            g_pk1[off] = run;
            run += g_ck1[off];
        }
    }
}

// ---------------------------------------------------------------------------
// Chunk partial (inter-chunk): g_att = Q @ Sp (partial), g_den = q . k1prefix
// ---------------------------------------------------------------------------
#define QS   68
#define PART_SMEM ((CHUNK * QS + HD * QS + HD) * 4)

__global__ void __launch_bounds__(256) chunk_partial_kernel()
{
    extern __shared__ __align__(16) float sm[];
    float* Qs  = sm;
    float* Sps = sm + CHUNK * QS;
    float* k1s = Sps + HD * QS;

    const int bh = blockIdx.y, c = blockIdx.x;
    const int b = bh >> 4, hh = bh & 15;
    const int tid = threadIdx.x;
    const size_t base = ((size_t)(b * S_LEN + c * CHUNK)) * DIMV + hh * HD;
    const float* spg = g_pkv + ((size_t)bh * NCHUNK + c) * HD * HD;

#pragma unroll
    for (int it = 0; it < 8; it++) {
        const int idx = tid + it * 256;
        const int t = idx >> 4, dv = idx & 15;
        *(float4*)&Qs[t * QS + dv * 4] =
            *(const float4*)(g_q + base + (size_t)t * DIMV + dv * 4);
    }
#pragma unroll
    for (int it = 0; it < 4; it++) {
        const int idx = tid + it * 256;
        const int d1 = idx >> 4, dv = idx & 15;
        *(float4*)&Sps[d1 * QS + dv * 4] = *(const float4*)(spg + d1 * HD + dv * 4);
    }
    if (tid < HD) k1s[tid] = g_pk1[((size_t)bh * NCHUNK + c) * HD + tid];
    __syncthreads();

    const int tx = tid & 15, ty = tid >> 4;
    float acc[8][4];
#pragma unroll
    for (int i = 0; i < 8; i++)
#pragma unroll
        for (int j = 0; j < 4; j++) acc[i][j] = 0.f;

#pragma unroll 4
    for (int d1 = 0; d1 < HD; d1++) {
        float vf[4];
        *(float4*)vf = *(const float4*)&Sps[d1 * QS + tx * 4];
#pragma unroll
        for (int i = 0; i < 8; i++) {
            const float a = Qs[(ty * 8 + i) * QS + d1];
#pragma unroll
            for (int j = 0; j < 4; j++) acc[i][j] = fmaf(a, vf[j], acc[i][j]);
        }
    }

#pragma unroll
    for (int i = 0; i < 8; i++) {
        const int t = ty * 8 + i;
        *(float4*)(g_att + base + (size_t)t * DIMV + tx * 4) = *(float4*)acc[i];
    }

    if (tid < CHUNK) {
        float s = 0.f;
#pragma unroll 8
        for (int d = 0; d < HD; d++) s = fmaf(Qs[tid * QS + d], k1s[d], s);
        g_den[((size_t)bh * NCHUNK + c) * CHUNK + tid] = s;
    }
}

// ---------------------------------------------------------------------------
// Chunk output (intra-chunk): A = QK^T masked; out = (partial + A@V)/den.
// Am overlays QsT+KsT after phase 2. smem 98KB -> 2 CTAs/SM.
// ---------------------------------------------------------------------------
#define COUT_SMEM ((2 * HD * SMS + CHUNK * HD) * 4)

__global__ void __launch_bounds__(256, 2) chunk_out_kernel()
{
    extern __shared__ __align__(16) float sm[];
    float* QsT = sm;
    float* KsT = sm + HD * SMS;
    float* Am  = sm;
    float* Vs  = sm + 2 * HD * SMS;
    __shared__ float dens[CHUNK];

    const int bh = blockIdx.y, c = blockIdx.x;
    const int b = bh >> 4, hh = bh & 15;
    const int tid = threadIdx.x;
    const size_t base = ((size_t)(b * S_LEN + c * CHUNK)) * DIMV + hh * HD;

#pragma unroll
    for (int it = 0; it < 8; it++) {
        const int idx = tid + it * 256;
        const int t = idx >> 4, dv = idx & 15;
        float4 q4 = *(const float4*)(g_q + base + (size_t)t * DIMV + dv * 4);
        float4 k4 = *(const float4*)(g_k + base + (size_t)t * DIMV + dv * 4);
        float4 v4 = *(const float4*)(g_v + base + (size_t)t * DIMV + dv * 4);
        QsT[(dv * 4 + 0) * SMS + t] = q4.x;
        QsT[(dv * 4 + 1) * SMS + t] = q4.y;
        QsT[(dv * 4 + 2) * SMS + t] = q4.z;
        QsT[(dv * 4 + 3) * SMS + t] = q4.w;
        KsT[(dv * 4 + 0) * SMS + t] = k4.x;
        KsT[(dv * 4 + 1) * SMS + t] = k4.y;
        KsT[(dv * 4 + 2) * SMS + t] = k4.z;
        KsT[(dv * 4 + 3) * SMS + t] = k4.w;
        *(float4*)&Vs[t * HD + dv * 4] = v4;
    }
    __syncthreads();

    const int tx = tid & 15, ty = tid >> 4;

    float acc[8][8];
#pragma unroll
    for (int i = 0; i < 8; i++)
#pragma unroll
        for (int j = 0; j < 8; j++) acc[i][j] = 0.f;
#pragma unroll 4
    for (int kk = 0; kk < HD; kk++) {
        float qf[8], kf[8];
        *(float4*)(qf)     = *(const float4*)&QsT[kk * SMS + ty * 8];
        *(float4*)(qf + 4) = *(const float4*)&QsT[kk * SMS + ty * 8 + 4];
        *(float4*)(kf)     = *(const float4*)&KsT[kk * SMS + tx * 8];
        *(float4*)(kf + 4) = *(const float4*)&KsT[kk * SMS + tx * 8 + 4];
#pragma unroll
        for (int i = 0; i < 8; i++)
#pragma unroll
            for (int j = 0; j < 8; j++)
                acc[i][j] = fmaf(qf[i], kf[j], acc[i][j]);
    }
    __syncthreads();

#pragma unroll
    for (int i = 0; i < 8; i++) {
        const int t = ty * 8 + i;
        float o[8];
#pragma unroll
        for (int j = 0; j < 8; j++) {
            const int tp = tx * 8 + j;
            o[j] = (tp <= t) ? acc[i][j] : 0.f;
        }
        *(float4*)&Am[t * SMS + tx * 8]     = *(float4*)o;
        *(float4*)&Am[t * SMS + tx * 8 + 4] = *(float4*)(o + 4);
    }
    __syncthreads();

    if (tid < CHUNK) {
        float s = g_den[((size_t)bh * NCHUNK + c) * CHUNK + tid];
#pragma unroll 8
        for (int tp0 = 0; tp0 < CHUNK; tp0++) {
            const int tp = (tp0 + tid) & (CHUNK - 1);
            s += Am[tid * SMS + tp];
        }
        dens[tid] = 1.0f / s;
    }
    __syncthreads();

    float acc2[8][4];
#pragma unroll
    for (int i = 0; i < 8; i++)
#pragma unroll
        for (int j = 0; j < 4; j++) acc2[i][j] = 0.f;
#pragma unroll 4
    for (int tp = 0; tp < CHUNK; tp++) {
        float vf[4];
        *(float4*)vf = *(const float4*)&Vs[tp * HD + tx * 4];
#pragma unroll
        for (int i = 0; i < 8; i++) {
            const float a = Am[(ty * 8 + i) * SMS + tp];
#pragma unroll
            for (int j = 0; j < 4; j++) acc2[i][j] = fmaf(a, vf[j], acc2[i][j]);
        }
    }
#pragma unroll
    for (int i = 0; i < 8; i++) {
        const int t = ty * 8 + i;
        const float inv = dens[t];
        float4 p = *(const float4*)(g_att + base + (size_t)t * DIMV + tx * 4);
        float4 o;
        o.x = (acc2[i][0] + p.x) * inv;
        o.y = (acc2[i][1] + p.y) * inv;
        o.z = (acc2[i][2] + p.z) * inv;
        o.w = (acc2[i][3] + p.w) * inv;
        *(float4*)(g_att + base + (size_t)t * DIMV + tx * 4) = o;
    }
}

// ---------------------------------------------------------------------------
// Launch
// ---------------------------------------------------------------------------
extern "C" void kernel_launch(void* const* d_in, const int* in_sizes, int n_in,
                              void* d_out, int out_size)
{
    const float* x  = (const float*)d_in[0];
    const float* Wq = (const float*)d_in[1];
    const float* bq = (const float*)d_in[2];
    const float* Wk = (const float*)d_in[3];
    const float* bk = (const float*)d_in[4];
    const float* Wv = (const float*)d_in[5];
    const float* bv = (const float*)d_in[6];
    const float* Wo = (const float*)d_in[7];
    const float* bo = (const float*)d_in[8];
    float* out = (float*)d_out;

    const int stats_smem = 2 * CHUNK * HD * (int)sizeof(float);
    cudaFuncSetAttribute(qk_mma_kernel,
                         cudaFuncAttributeMaxDynamicSharedMemorySize, GSM);
    cudaFuncSetAttribute(v_mma_kernel,
                         cudaFuncAttributeMaxDynamicSharedMemorySize, GSM);
    cudaFuncSetAttribute(out_mma_kernel,
                         cudaFuncAttributeMaxDynamicSharedMemorySize, GSM);
    cudaFuncSetAttribute(chunk_stats_kernel,
                         cudaFuncAttributeMaxDynamicSharedMemorySize, stats_smem);
    cudaFuncSetAttribute(chunk_partial_kernel,
                         cudaFuncAttributeMaxDynamicSharedMemorySize, PART_SMEM);
    cudaFuncSetAttribute(chunk_out_kernel,
                         cudaFuncAttributeMaxDynamicSharedMemorySize, COUT_SMEM);

    // 1. fp16 hi/lo prep
    split_act16_kernel<<<512, 256>>>(x);
    split_w16_kernel<<<256, 256>>>(Wq, 0);
    split_w16_kernel<<<256, 256>>>(Wk, 1);
    split_w16_kernel<<<256, 256>>>(Wv, 2);
    split_w16_kernel<<<256, 256>>>(Wo, 3);

    // 2. projections: Q,K 3-pass + exp; V 2-pass
    qk_mma_kernel<<<dim3(NDIM / 64, M_ROWS / 128, 2), 256, GSM>>>(bq, bk);
    v_mma_kernel<<<dim3(NDIM / 64, M_ROWS / 128), 256, GSM>>>(bv);

    // 3. chunked linear attention
    chunk_stats_kernel<<<dim3(NCHUNK, BHEADS), 256, stats_smem>>>();
    prefix_kernel<<<BHEADS, 256>>>();
    chunk_partial_kernel<<<dim3(NCHUNK, BHEADS), 256, PART_SMEM>>>();
    chunk_out_kernel<<<dim3(NCHUNK, BHEADS), 256, COUT_SMEM>>>();

    // 4. output projection: 2-pass
    split_att16_kernel<<<512, 256>>>();
    out_mma_kernel<<<dim3(NDIM / 64, M_ROWS / 128), 256, GSM>>>(bo, out);
}

// round 16
// speedup vs baseline: 2.1862x; 1.1377x over previous
#include <cuda_runtime.h>
#include <cuda_fp16.h>
#include <cstdint>

// Problem constants
#define S_LEN  2048
#define DIMV   1024
#define NHEAD  16
#define HD     64
#define BATCH  2
#define M_ROWS (BATCH * S_LEN)     // 4096
#define KDIM   1024
#define NDIM   1024
#define BHEADS (BATCH * NHEAD)     // 32
#define CHUNK  128
#define NCHUNK (S_LEN / CHUNK)     // 16
#define WSZ    (NDIM * KDIM)

// ---------------------------------------------------------------------------
// Scratch (static device globals)
// ---------------------------------------------------------------------------
__device__ float g_q[M_ROWS * DIMV];
__device__ float g_k[M_ROWS * DIMV];
__device__ float g_v[M_ROWS * DIMV];
__device__ float g_att[M_ROWS * DIMV];        // inter-chunk partial only
__device__ float g_ckv[BHEADS * NCHUNK * HD * HD];
__device__ float g_ck1[BHEADS * NCHUNK * HD];
__device__ float g_pkv[BHEADS * NCHUNK * HD * HD];
__device__ float g_pk1[BHEADS * NCHUNK * HD];
__device__ float g_den[BHEADS * NCHUNK * CHUNK];
__device__ __half g_ah16[M_ROWS * KDIM];      // activation hi (x, then att)
__device__ __half g_wh16[4 * WSZ];            // weight hi: Wq,Wk,Wv,Wo
__device__ __half g_wl16[4 * WSZ];            // weight lo

#define SMS 132  // padded shared stride for the fp32 attention kernels

// ===========================================================================
// Helpers
// ===========================================================================
__device__ __forceinline__ uint32_t smem_u32(const void* p) {
    uint32_t a;
    asm("{ .reg .u64 t; cvta.to.shared.u64 t, %1; cvt.u32.u64 %0, t; }"
        : "=r"(a) : "l"(p));
    return a;
}

__device__ __forceinline__ uint32_t h2u(__half2 h) {
    return *reinterpret_cast<uint32_t*>(&h);
}

__device__ __forceinline__ void mma_f16(float* d, const uint32_t* a,
                                        uint32_t b0, uint32_t b1) {
    asm volatile(
        "mma.sync.aligned.m16n8k16.row.col.f32.f16.f16.f32 "
        "{%0,%1,%2,%3}, {%4,%5,%6,%7}, {%8,%9}, {%0,%1,%2,%3};"
        : "+f"(d[0]), "+f"(d[1]), "+f"(d[2]), "+f"(d[3])
        : "r"(a[0]), "r"(a[1]), "r"(a[2]), "r"(a[3]), "r"(b0), "r"(b1));
}

// 8 fp32 -> 4 fp16x2 hi only
__device__ __forceinline__ void cvt8_hi(float4 a, float4 b, uint4& hi)
{
    __half2 h0 = __floats2half2_rn(a.x, a.y);
    __half2 h1 = __floats2half2_rn(a.z, a.w);
    __half2 h2 = __floats2half2_rn(b.x, b.y);
    __half2 h3 = __floats2half2_rn(b.z, b.w);
    hi.x = h2u(h0); hi.y = h2u(h1); hi.z = h2u(h2); hi.w = h2u(h3);
}

// 8 fp32 -> hi + lo residual
__device__ __forceinline__ void cvt8(float4 a, float4 b, uint4& hi, uint4& lo)
{
    __half2 h0 = __floats2half2_rn(a.x, a.y);
    __half2 h1 = __floats2half2_rn(a.z, a.w);
    __half2 h2 = __floats2half2_rn(b.x, b.y);
    __half2 h3 = __floats2half2_rn(b.z, b.w);
    float2 f0 = __half22float2(h0);
    float2 f1 = __half22float2(h1);
    float2 f2 = __half22float2(h2);
    float2 f3 = __half22float2(h3);
    __half2 l0 = __floats2half2_rn(a.x - f0.x, a.y - f0.y);
    __half2 l1 = __floats2half2_rn(a.z - f1.x, a.w - f1.y);
    __half2 l2 = __floats2half2_rn(b.x - f2.x, b.y - f2.y);
    __half2 l3 = __floats2half2_rn(b.z - f3.x, b.w - f3.y);
    hi.x = h2u(h0); hi.y = h2u(h1); hi.z = h2u(h2); hi.w = h2u(h3);
    lo.x = h2u(l0); lo.y = h2u(l1); lo.z = h2u(l2); lo.w = h2u(l3);
}

__device__ __forceinline__ void cp16(uint32_t saddr, const void* g) {
    asm volatile("cp.async.cg.shared.global [%0], [%1], 16;"
                 :: "r"(saddr), "l"(g));
}
#define CP_COMMIT() asm volatile("cp.async.commit_group;" ::: "memory")
#define CP_WAIT1()  asm volatile("cp.async.wait_group 1;" ::: "memory")
#define CP_WAIT0()  asm volatile("cp.async.wait_group 0;" ::: "memory")

// ---------------------------------------------------------------------------
// Prep kernels
// ---------------------------------------------------------------------------
__global__ void __launch_bounds__(256) split_act_hi_kernel(const float* __restrict__ src)
{
    const int n8 = M_ROWS * KDIM / 8;
    int i = blockIdx.x * blockDim.x + threadIdx.x;
    const int stride = gridDim.x * blockDim.x;
    for (; i < n8; i += stride) {
        const float4 a = ((const float4*)src)[2 * i];
        const float4 b = ((const float4*)src)[2 * i + 1];
        uint4 h;
        cvt8_hi(a, b, h);
        ((uint4*)g_ah16)[i] = h;
    }
}

__global__ void __launch_bounds__(256) split_w16_kernel(const float* __restrict__ src, int slot)
{
    __half* hi = g_wh16 + (size_t)slot * WSZ;
    __half* lo = g_wl16 + (size_t)slot * WSZ;
    const int n8 = WSZ / 8;
    int i = blockIdx.x * blockDim.x + threadIdx.x;
    const int stride = gridDim.x * blockDim.x;
    for (; i < n8; i += stride) {
        const float4 a = ((const float4*)src)[2 * i];
        const float4 b = ((const float4*)src)[2 * i + 1];
        uint4 h, l;
        cvt8(a, b, h, l);
        ((uint4*)hi)[i] = h;
        ((uint4*)lo)[i] = l;
    }
}

// ===========================================================================
// 2-pass fp16 GEMM: C = ah*(bh+bl) + bias, optional exp.
// cp.async 3-stage ring, BK=32. CTA 128x64, 8 warps 4x2, 32x32 warp tiles.
// Smem row stride 20 words (16 data + 4 pad): fragment LDS conflict-free.
// ===========================================================================
#define BK32  32
#define NKS32 (KDIM / BK32)   // 32
#define RW    20
#define TA    (128 * RW)      // 2560 words: A hi tile
#define TB    (64 * RW)       // 1280 words: B tile (hi or lo)
#define OAH   0
#define OBH   TA
#define OBL   (TA + TB)
#define STW   (TA + 2 * TB)          // 5120 words per stage
#define GSM   (3 * STW * 4)          // 61440 bytes

__device__ __forceinline__ void gemm2p(
    const __half* __restrict__ Ah,
    const __half* __restrict__ Bh, const __half* __restrict__ Bl,
    const float* __restrict__ bias, float* __restrict__ out, int doExp,
    int m0, int n0)
{
    extern __shared__ uint32_t su[];
    const uint32_t shb = smem_u32(su);

    const int tid = threadIdx.x;
    const int lane = tid & 31, wid = tid >> 5;
    const int wm = wid >> 1, wn = wid & 1;       // 4 x 2 warp grid
    const int grp = lane >> 2, tig = lane & 3;

    const int rA = tid >> 1, hA = tid & 1;
    const __half* pAh = Ah + (size_t)(m0 + rA) * KDIM + hA * 16;
    const uint32_t sA = (uint32_t)(rA * RW + hA * 8) * 4u;
    const int rB = tid >> 2, qB = tid & 3;
    const __half* pBh = Bh + (size_t)(n0 + rB) * KDIM + qB * 8;
    const __half* pBl = Bl + (size_t)(n0 + rB) * KDIM + qB * 8;
    const uint32_t sB = (uint32_t)(rB * RW + qB * 4) * 4u;

    float acc[2][4][4];
#pragma unroll
    for (int mt = 0; mt < 2; mt++)
#pragma unroll
        for (int nt = 0; nt < 4; nt++)
#pragma unroll
            for (int e = 0; e < 4; e++) acc[mt][nt][e] = 0.f;

#define ISSUE(s_) do {                                                   \
    const int s__ = (s_);                                                \
    const int k0__ = s__ * BK32;                                         \
    const uint32_t sb__ = shb + (uint32_t)((s__ % 3) * STW) * 4u;        \
    cp16(sb__ + OAH * 4 + sA,      pAh + k0__);                          \
    cp16(sb__ + OAH * 4 + sA + 16, pAh + k0__ + 8);                      \
    cp16(sb__ + OBH * 4 + sB,      pBh + k0__);                          \
    cp16(sb__ + OBL * 4 + sB,      pBl + k0__);                          \
    CP_COMMIT();                                                         \
} while (0)

    ISSUE(0);
    ISSUE(1);

    for (int s = 0; s < NKS32; s++) {
        if (s + 1 < NKS32) CP_WAIT1(); else CP_WAIT0();
        __syncthreads();
        if (s + 2 < NKS32) ISSUE(s + 2);

        const uint32_t* bu = su + (s % 3) * STW;
#pragma unroll
        for (int k16 = 0; k16 < 2; k16++) {
            const int wb = k16 * 8;
            uint32_t ah[2][4];
#pragma unroll
            for (int mt = 0; mt < 2; mt++) {
                const int ro = (wm * 32 + mt * 16 + grp) * RW;
                ah[mt][0] = bu[OAH + ro + wb + tig];
                ah[mt][1] = bu[OAH + ro + 8 * RW + wb + tig];
                ah[mt][2] = bu[OAH + ro + wb + tig + 4];
                ah[mt][3] = bu[OAH + ro + 8 * RW + wb + tig + 4];
            }
#pragma unroll
            for (int nt = 0; nt < 4; nt++) {
                const int ro = (wn * 32 + nt * 8 + grp) * RW;
                const uint32_t bh0 = bu[OBH + ro + wb + tig];
                const uint32_t bh1 = bu[OBH + ro + wb + tig + 4];
                const uint32_t bl0 = bu[OBL + ro + wb + tig];
                const uint32_t bl1 = bu[OBL + ro + wb + tig + 4];
#pragma unroll
                for (int mt = 0; mt < 2; mt++) {
                    mma_f16(acc[mt][nt], ah[mt], bh0, bh1);
                    mma_f16(acc[mt][nt], ah[mt], bl0, bl1);
                }
            }
        }
        __syncthreads();
    }
#undef ISSUE

    // epilogue
#pragma unroll
    for (int mt = 0; mt < 2; mt++) {
        const int rr = m0 + wm * 32 + mt * 16 + grp;
#pragma unroll
        for (int nt = 0; nt < 4; nt++) {
            const int cc = n0 + wn * 32 + nt * 8 + 2 * tig;
            const float bb0 = bias[cc], bb1 = bias[cc + 1];
            float v0 = acc[mt][nt][0] + bb0;
            float v1 = acc[mt][nt][1] + bb1;
            float v2 = acc[mt][nt][2] + bb0;
            float v3 = acc[mt][nt][3] + bb1;
            if (doExp) {
                v0 = expf(v0); v1 = expf(v1); v2 = expf(v2); v3 = expf(v3);
            }
            float2 p0; p0.x = v0; p0.y = v1;
            float2 p1; p1.x = v2; p1.y = v3;
            *(float2*)&out[(size_t)rr * NDIM + cc]       = p0;
            *(float2*)&out[(size_t)(rr + 8) * NDIM + cc] = p1;
        }
    }
}

__global__ void __launch_bounds__(256, 2) qkv_mma_kernel(
    const float* __restrict__ bq, const float* __restrict__ bk,
    const float* __restrict__ bv)
{
    const int z = blockIdx.z;
    const float* bias = (z == 0) ? bq : ((z == 1) ? bk : bv);
    float* out        = (z == 0) ? g_q : ((z == 1) ? g_k : g_v);
    gemm2p(g_ah16, g_wh16 + (size_t)z * WSZ, g_wl16 + (size_t)z * WSZ,
           bias, out, z < 2, blockIdx.y * 128, blockIdx.x * 64);
}

__global__ void __launch_bounds__(256, 2) out_mma_kernel(
    const float* __restrict__ bo, float* __restrict__ out)
{
    gemm2p(g_ah16, g_wh16 + (size_t)3 * WSZ, g_wl16 + (size_t)3 * WSZ,
           bo, out, 0, blockIdx.y * 128, blockIdx.x * 64);
}

// ---------------------------------------------------------------------------
// Chunk stats: per (head, chunk) compute sum_t k_t v_t^T (64x64) and sum_t k_t
// ---------------------------------------------------------------------------
__global__ void __launch_bounds__(256) chunk_stats_kernel()
{
    extern __shared__ __align__(16) float sm[];
    float* Ks = sm;
    float* Vs = sm + CHUNK * HD;
    const int bh = blockIdx.y, c = blockIdx.x;
    const int b = bh >> 4, hh = bh & 15;
    const int tid = threadIdx.x;
    const size_t base = ((size_t)(b * S_LEN + c * CHUNK)) * DIMV + hh * HD;

#pragma unroll
    for (int it = 0; it < 8; it++) {
        const int idx = tid + it * 256;
        const int t = idx >> 4, dv = idx & 15;
        *(float4*)&Ks[t * HD + dv * 4] =
            *(const float4*)(g_k + base + (size_t)t * DIMV + dv * 4);
        *(float4*)&Vs[t * HD + dv * 4] =
            *(const float4*)(g_v + base + (size_t)t * DIMV + dv * 4);
    }
    __syncthreads();

    const int tx = tid & 15, ty = tid >> 4;
    float acc[4][4];
#pragma unroll
    for (int i = 0; i < 4; i++)
#pragma unroll
        for (int j = 0; j < 4; j++) acc[i][j] = 0.f;

#pragma unroll 4
    for (int t = 0; t < CHUNK; t++) {
        float kf[4], vf[4];
        *(float4*)kf = *(const float4*)&Ks[t * HD + ty * 4];
        *(float4*)vf = *(const float4*)&Vs[t * HD + tx * 4];
#pragma unroll
        for (int i = 0; i < 4; i++)
#pragma unroll
            for (int j = 0; j < 4; j++)
                acc[i][j] = fmaf(kf[i], vf[j], acc[i][j]);
    }

    float* okv = g_ckv + ((size_t)bh * NCHUNK + c) * HD * HD;
#pragma unroll
    for (int i = 0; i < 4; i++)
        *(float4*)&okv[(ty * 4 + i) * HD + tx * 4] = *(float4*)acc[i];

    if (tid < HD) {
        float s = 0.f;
#pragma unroll 8
        for (int t = 0; t < CHUNK; t++) s += Ks[t * HD + tid];
        g_ck1[((size_t)bh * NCHUNK + c) * HD + tid] = s;
    }
}

// ---------------------------------------------------------------------------
// Exclusive prefix over the 16 chunk states per head
// ---------------------------------------------------------------------------
__global__ void __launch_bounds__(256) prefix_kernel()
{
    const int bh = blockIdx.x, tid = threadIdx.x;
    for (int e = tid; e < HD * HD; e += 256) {
        float run = 0.f;
#pragma unroll
        for (int c = 0; c < NCHUNK; c++) {
            const size_t off = ((size_t)bh * NCHUNK + c) * HD * HD + e;
            g_pkv[off] = run;
            run += g_ckv[off];
        }
    }
    if (tid < HD) {
        float run = 0.f;
#pragma unroll
        for (int c = 0; c < NCHUNK; c++) {
            const size_t off = ((size_t)bh * NCHUNK + c) * HD + tid;
            g_pk1[off] = run;
            run += g_ck1[off];
        }
    }
}

// ---------------------------------------------------------------------------
// Chunk partial (inter-chunk): g_att = Q @ Sp (partial), g_den = q . k1prefix
// ---------------------------------------------------------------------------
#define QS   68
#define PART_SMEM ((CHUNK * QS + HD * QS + HD) * 4)

__global__ void __launch_bounds__(256) chunk_partial_kernel()
{
    extern __shared__ __align__(16) float sm[];
    float* Qs  = sm;
    float* Sps = sm + CHUNK * QS;
    float* k1s = Sps + HD * QS;

    const int bh = blockIdx.y, c = blockIdx.x;
    const int b = bh >> 4, hh = bh & 15;
    const int tid = threadIdx.x;
    const size_t base = ((size_t)(b * S_LEN + c * CHUNK)) * DIMV + hh * HD;
    const float* spg = g_pkv + ((size_t)bh * NCHUNK + c) * HD * HD;

#pragma unroll
    for (int it = 0; it < 8; it++) {
        const int idx = tid + it * 256;
        const int t = idx >> 4, dv = idx & 15;
        *(float4*)&Qs[t * QS + dv * 4] =
            *(const float4*)(g_q + base + (size_t)t * DIMV + dv * 4);
    }
#pragma unroll
    for (int it = 0; it < 4; it++) {
        const int idx = tid + it * 256;
        const int d1 = idx >> 4, dv = idx & 15;
        *(float4*)&Sps[d1 * QS + dv * 4] = *(const float4*)(spg + d1 * HD + dv * 4);
    }
    if (tid < HD) k1s[tid] = g_pk1[((size_t)bh * NCHUNK + c) * HD + tid];
    __syncthreads();

    const int tx = tid & 15, ty = tid >> 4;
    float acc[8][4];
#pragma unroll
    for (int i = 0; i < 8; i++)
#pragma unroll
        for (int j = 0; j < 4; j++) acc[i][j] = 0.f;

#pragma unroll 4
    for (int d1 = 0; d1 < HD; d1++) {
        float vf[4];
        *(float4*)vf = *(const float4*)&Sps[d1 * QS + tx * 4];
#pragma unroll
        for (int i = 0; i < 8; i++) {
            const float a = Qs[(ty * 8 + i) * QS + d1];
#pragma unroll
            for (int j = 0; j < 4; j++) acc[i][j] = fmaf(a, vf[j], acc[i][j]);
        }
    }

#pragma unroll
    for (int i = 0; i < 8; i++) {
        const int t = ty * 8 + i;
        *(float4*)(g_att + base + (size_t)t * DIMV + tx * 4) = *(float4*)acc[i];
    }

    if (tid < CHUNK) {
        float s = 0.f;
#pragma unroll 8
        for (int d = 0; d < HD; d++) s = fmaf(Qs[tid * QS + d], k1s[d], s);
        g_den[((size_t)bh * NCHUNK + c) * CHUNK + tid] = s;
    }
}

// ---------------------------------------------------------------------------
// Chunk output (intra-chunk): A = QK^T masked; att = (partial + A@V)/den,
// written DIRECTLY as fp16 hi into g_ah16 (feeds 2-pass out-projection).
// Am overlays QsT+KsT after phase 2. smem 98KB -> 2 CTAs/SM.
// ---------------------------------------------------------------------------
#define COUT_SMEM ((2 * HD * SMS + CHUNK * HD) * 4)

__global__ void __launch_bounds__(256, 2) chunk_out_kernel()
{
    extern __shared__ __align__(16) float sm[];
    float* QsT = sm;
    float* KsT = sm + HD * SMS;
    float* Am  = sm;
    float* Vs  = sm + 2 * HD * SMS;
    __shared__ float dens[CHUNK];

    const int bh = blockIdx.y, c = blockIdx.x;
    const int b = bh >> 4, hh = bh & 15;
    const int tid = threadIdx.x;
    const size_t base = ((size_t)(b * S_LEN + c * CHUNK)) * DIMV + hh * HD;

#pragma unroll
    for (int it = 0; it < 8; it++) {
        const int idx = tid + it * 256;
        const int t = idx >> 4, dv = idx & 15;
        float4 q4 = *(const float4*)(g_q + base + (size_t)t * DIMV + dv * 4);
        float4 k4 = *(const float4*)(g_k + base + (size_t)t * DIMV + dv * 4);
        float4 v4 = *(const float4*)(g_v + base + (size_t)t * DIMV + dv * 4);
        QsT[(dv * 4 + 0) * SMS + t] = q4.x;
        QsT[(dv * 4 + 1) * SMS + t] = q4.y;
        QsT[(dv * 4 + 2) * SMS + t] = q4.z;
        QsT[(dv * 4 + 3) * SMS + t] = q4.w;
        KsT[(dv * 4 + 0) * SMS + t] = k4.x;
        KsT[(dv * 4 + 1) * SMS + t] = k4.y;
        KsT[(dv * 4 + 2) * SMS + t] = k4.z;
        KsT[(dv * 4 + 3) * SMS + t] = k4.w;
        *(float4*)&Vs[t * HD + dv * 4] = v4;
    }
    __syncthreads();

    const int tx = tid & 15, ty = tid >> 4;

    float acc[8][8];
#pragma unroll
    for (int i = 0; i < 8; i++)
#pragma unroll
        for (int j = 0; j < 8; j++) acc[i][j] = 0.f;
#pragma unroll 4
    for (int kk = 0; kk < HD; kk++) {
        float qf[8], kf[8];
        *(float4*)(qf)     = *(const float4*)&QsT[kk * SMS + ty * 8];
        *(float4*)(qf + 4) = *(const float4*)&QsT[kk * SMS + ty * 8 + 4];
        *(float4*)(kf)     = *(const float4*)&KsT[kk * SMS + tx * 8];
        *(float4*)(kf + 4) = *(const float4*)&KsT[kk * SMS + tx * 8 + 4];
#pragma unroll
        for (int i = 0; i < 8; i++)
#pragma unroll
            for (int j = 0; j < 8; j++)
                acc[i][j] = fmaf(qf[i], kf[j], acc[i][j]);
    }
    __syncthreads();

#pragma unroll
    for (int i = 0; i < 8; i++) {
        const int t = ty * 8 + i;
        float o[8];
#pragma unroll
        for (int j = 0; j < 8; j++) {
            const int tp = tx * 8 + j;
            o[j] = (tp <= t) ? acc[i][j] : 0.f;
        }
        *(float4*)&Am[t * SMS + tx * 8]     = *(float4*)o;
        *(float4*)&Am[t * SMS + tx * 8 + 4] = *(float4*)(o + 4);
    }
    __syncthreads();

    if (tid < CHUNK) {
        float s = g_den[((size_t)bh * NCHUNK + c) * CHUNK + tid];
#pragma unroll 8
        for (int tp0 = 0; tp0 < CHUNK; tp0++) {
            const int tp = (tp0 + tid) & (CHUNK - 1);
            s += Am[tid * SMS + tp];
        }
        dens[tid] = 1.0f / s;
    }
    __syncthreads();

    float acc2[8][4];
#pragma unroll
    for (int i = 0; i < 8; i++)
#pragma unroll
        for (int j = 0; j < 4; j++) acc2[i][j] = 0.f;
#pragma unroll 4
    for (int tp = 0; tp < CHUNK; tp++) {
        float vf[4];
        *(float4*)vf = *(const float4*)&Vs[tp * HD + tx * 4];
#pragma unroll
        for (int i = 0; i < 8; i++) {
            const float a = Am[(ty * 8 + i) * SMS + tp];
#pragma unroll
            for (int j = 0; j < 4; j++) acc2[i][j] = fmaf(a, vf[j], acc2[i][j]);
        }
    }
#pragma unroll
    for (int i = 0; i < 8; i++) {
        const int t = ty * 8 + i;
        const float inv = dens[t];
        float4 p = *(const float4*)(g_att + base + (size_t)t * DIMV + tx * 4);
        const float o0 = (acc2[i][0] + p.x) * inv;
        const float o1 = (acc2[i][1] + p.y) * inv;
        const float o2 = (acc2[i][2] + p.z) * inv;
        const float o3 = (acc2[i][3] + p.w) * inv;
        __half2 ha = __floats2half2_rn(o0, o1);
        __half2 hb = __floats2half2_rn(o2, o3);
        uint2 u; u.x = h2u(ha); u.y = h2u(hb);
        *(uint2*)(g_ah16 + base + (size_t)t * DIMV + tx * 4) = u;
    }
}

// ---------------------------------------------------------------------------
// Launch
// ---------------------------------------------------------------------------
extern "C" void kernel_launch(void* const* d_in, const int* in_sizes, int n_in,
                              void* d_out, int out_size)
{
    const float* x  = (const float*)d_in[0];
    const float* Wq = (const float*)d_in[1];
    const float* bq = (const float*)d_in[2];
    const float* Wk = (const float*)d_in[3];
    const float* bk = (const float*)d_in[4];
    const float* Wv = (const float*)d_in[5];
    const float* bv = (const float*)d_in[6];
    const float* Wo = (const float*)d_in[7];
    const float* bo = (const float*)d_in[8];
    float* out = (float*)d_out;

    const int stats_smem = 2 * CHUNK * HD * (int)sizeof(float);
    cudaFuncSetAttribute(qkv_mma_kernel,
                         cudaFuncAttributeMaxDynamicSharedMemorySize, GSM);
    cudaFuncSetAttribute(out_mma_kernel,
                         cudaFuncAttributeMaxDynamicSharedMemorySize, GSM);
    cudaFuncSetAttribute(chunk_stats_kernel,
                         cudaFuncAttributeMaxDynamicSharedMemorySize, stats_smem);
    cudaFuncSetAttribute(chunk_partial_kernel,
                         cudaFuncAttributeMaxDynamicSharedMemorySize, PART_SMEM);
    cudaFuncSetAttribute(chunk_out_kernel,
                         cudaFuncAttributeMaxDynamicSharedMemorySize, COUT_SMEM);

    // 1. prep: activations hi-only; weights hi+lo
    split_act_hi_kernel<<<512, 256>>>(x);
    split_w16_kernel<<<256, 256>>>(Wq, 0);
    split_w16_kernel<<<256, 256>>>(Wk, 1);
    split_w16_kernel<<<256, 256>>>(Wv, 2);
    split_w16_kernel<<<256, 256>>>(Wo, 3);

    // 2. QKV projections, all 2-pass (+exp for q,k)
    qkv_mma_kernel<<<dim3(NDIM / 64, M_ROWS / 128, 3), 256, GSM>>>(bq, bk, bv);

    // 3. chunked linear attention (chunk_out writes fp16 att-hi directly)
    chunk_stats_kernel<<<dim3(NCHUNK, BHEADS), 256, stats_smem>>>();
    prefix_kernel<<<BHEADS, 256>>>();
    chunk_partial_kernel<<<dim3(NCHUNK, BHEADS), 256, PART_SMEM>>>();
    chunk_out_kernel<<<dim3(NCHUNK, BHEADS), 256, COUT_SMEM>>>();

    // 4. output projection, 2-pass
    out_mma_kernel<<<dim3(NDIM / 64, M_ROWS / 128), 256, GSM>>>(bo, out);
}